// round 2
// baseline (speedup 1.0000x reference)
#include <cuda_runtime.h>

// Problem constants
#define BATCH   2
#define S_LEN   2048
#define D_MODEL 1024
#define NH      16
#define HD      64
#define MROWS   (BATCH * S_LEN)   // 4096

// Scratch (allocation-free rule: __device__ globals)
__device__ float g_Q[MROWS * D_MODEL];
__device__ float g_K[MROWS * D_MODEL];
__device__ float g_V[MROWS * D_MODEL];
__device__ float g_Ctx[MROWS * D_MODEL];

// ---------------------------------------------------------------------------
// Tiled SGEMM: C[M,N] = A[M,K] * B[K,N], row-major, fp32.
// BM=BN=128, BK=16, 256 threads, 8x8 per thread.
// ---------------------------------------------------------------------------
__global__ __launch_bounds__(256) void sgemm_kernel(
    const float* __restrict__ A, const float* __restrict__ B,
    float* __restrict__ C, int M, int N, int K)
{
    __shared__ float As[16][132];   // transposed A tile, padded
    __shared__ float Bs[16][128];

    const int tid = threadIdx.x;
    const int tx  = tid & 15;
    const int ty  = tid >> 4;
    const int m0  = blockIdx.y * 128;
    const int n0  = blockIdx.x * 128;

    float acc[8][8];
#pragma unroll
    for (int i = 0; i < 8; i++)
#pragma unroll
        for (int j = 0; j < 8; j++) acc[i][j] = 0.f;

    for (int kt = 0; kt < K; kt += 16) {
#pragma unroll
        for (int l = 0; l < 2; l++) {
            int idx = tid + l * 256;
            int row = idx >> 2;
            int kc  = (idx & 3) << 2;
            float4 a = *(const float4*)(A + (size_t)(m0 + row) * K + kt + kc);
            As[kc + 0][row] = a.x;
            As[kc + 1][row] = a.y;
            As[kc + 2][row] = a.z;
            As[kc + 3][row] = a.w;
        }
#pragma unroll
        for (int l = 0; l < 2; l++) {
            int idx = tid + l * 256;
            int row = idx >> 5;
            int col = (idx & 31) << 2;
            float4 b = *(const float4*)(B + (size_t)(kt + row) * N + n0 + col);
            *(float4*)&Bs[row][col] = b;
        }
        __syncthreads();

#pragma unroll
        for (int kk = 0; kk < 16; kk++) {
            float a[8], b[8];
            float4 a0 = *(const float4*)&As[kk][ty * 8];
            float4 a1 = *(const float4*)&As[kk][ty * 8 + 4];
            a[0]=a0.x; a[1]=a0.y; a[2]=a0.z; a[3]=a0.w;
            a[4]=a1.x; a[5]=a1.y; a[6]=a1.z; a[7]=a1.w;
            float4 b0 = *(const float4*)&Bs[kk][tx * 8];
            float4 b1 = *(const float4*)&Bs[kk][tx * 8 + 4];
            b[0]=b0.x; b[1]=b0.y; b[2]=b0.z; b[3]=b0.w;
            b[4]=b1.x; b[5]=b1.y; b[6]=b1.z; b[7]=b1.w;
#pragma unroll
            for (int i = 0; i < 8; i++)
#pragma unroll
                for (int j = 0; j < 8; j++)
                    acc[i][j] = fmaf(a[i], b[j], acc[i][j]);
        }
        __syncthreads();
    }

#pragma unroll
    for (int i = 0; i < 8; i++) {
        float* crow = C + (size_t)(m0 + ty * 8 + i) * N + n0 + tx * 8;
        *(float4*)(crow)     = make_float4(acc[i][0], acc[i][1], acc[i][2], acc[i][3]);
        *(float4*)(crow + 4) = make_float4(acc[i][4], acc[i][5], acc[i][6], acc[i][7]);
    }
}

// ---------------------------------------------------------------------------
// Causal flash attention, fp32. One block = 64 query rows of one (b,h),
// 64 threads (one per query row). q[64], o[64], and per-tile scores s[32]
// all in registers; K/V tiles of 32 keys in smem (16 KB total).
// ---------------------------------------------------------------------------
__global__ __launch_bounds__(64) void flash_kernel(
    const float* __restrict__ Qg, const float* __restrict__ Kg,
    const float* __restrict__ Vg, float* __restrict__ Ctx)
{
    __shared__ float Ks[32][64];
    __shared__ float Vs[32][64];

    const int b  = blockIdx.z;
    const int h  = blockIdx.y;
    const int q0 = blockIdx.x * 64;
    const int t  = threadIdx.x;
    const int qi = q0 + t;

    const size_t head_off = (size_t)h * HD;
    const float* qptr = Qg + ((size_t)(b * S_LEN + qi)) * D_MODEL + head_off;

    float q[64], o[64];
#pragma unroll
    for (int d = 0; d < 64; d += 4) {
        float4 v = *(const float4*)(qptr + d);
        q[d] = v.x; q[d+1] = v.y; q[d+2] = v.z; q[d+3] = v.w;
    }
#pragma unroll
    for (int d = 0; d < 64; d++) o[d] = 0.f;

    float mrun = -1e30f, lrun = 0.f;
    const float scale = 0.125f;   // 1/sqrt(64)

    // key tiles of 32; last two tiles (k0 in {q0, q0+32}) carry the diagonal
    for (int k0 = 0; k0 < q0 + 64; k0 += 32) {
        // load K/V tile: thread t loads half of key row (t>>1)
        const int krow = t >> 1;
        const int kcol = (t & 1) * 32;
        const float* kp = Kg + ((size_t)(b * S_LEN + k0 + krow)) * D_MODEL + head_off + kcol;
        const float* vp = Vg + ((size_t)(b * S_LEN + k0 + krow)) * D_MODEL + head_off + kcol;
        __syncthreads();
#pragma unroll
        for (int d = 0; d < 32; d += 4) {
            *(float4*)&Ks[krow][kcol + d] = *(const float4*)(kp + d);
            *(float4*)&Vs[krow][kcol + d] = *(const float4*)(vp + d);
        }
        __syncthreads();

        const bool needs_mask = (k0 + 31 > qi);
        float s[32];
        float mt = -1e30f;
#pragma unroll 4
        for (int j = 0; j < 32; j++) {
            const float4* k4 = (const float4*)Ks[j];
            float acc = 0.f;
#pragma unroll
            for (int d4 = 0; d4 < 16; d4++) {
                float4 kv = k4[d4];
                acc = fmaf(q[d4*4+0], kv.x, acc);
                acc = fmaf(q[d4*4+1], kv.y, acc);
                acc = fmaf(q[d4*4+2], kv.z, acc);
                acc = fmaf(q[d4*4+3], kv.w, acc);
            }
            acc *= scale;
            if (needs_mask && (k0 + j) > qi) acc = -1e30f;
            s[j] = acc;
            mt = fmaxf(mt, acc);
        }

        const float mnew  = fmaxf(mrun, mt);
        const float alpha = __expf(mrun - mnew);
        lrun *= alpha;
#pragma unroll
        for (int d = 0; d < 64; d++) o[d] *= alpha;

#pragma unroll 2
        for (int j = 0; j < 32; j++) {
            float p = __expf(s[j] - mnew);
            lrun += p;
            const float4* v4 = (const float4*)Vs[j];
#pragma unroll
            for (int d4 = 0; d4 < 16; d4++) {
                float4 vv = v4[d4];
                o[d4*4+0] = fmaf(p, vv.x, o[d4*4+0]);
                o[d4*4+1] = fmaf(p, vv.y, o[d4*4+1]);
                o[d4*4+2] = fmaf(p, vv.z, o[d4*4+2]);
                o[d4*4+3] = fmaf(p, vv.w, o[d4*4+3]);
            }
        }
        mrun = mnew;
    }

    const float inv = 1.f / lrun;
    float* op = Ctx + ((size_t)(b * S_LEN + qi)) * D_MODEL + head_off;
#pragma unroll
    for (int d = 0; d < 64; d += 4) {
        *(float4*)(op + d) = make_float4(o[d]*inv, o[d+1]*inv, o[d+2]*inv, o[d+3]*inv);
    }
}

// ---------------------------------------------------------------------------
extern "C" void kernel_launch(void* const* d_in, const int* in_sizes, int n_in,
                              void* d_out, int out_size)
{
    const float* X  = (const float*)d_in[0];
    const float* Wq = (const float*)d_in[1];
    const float* Wk = (const float*)d_in[2];
    const float* Wv = (const float*)d_in[3];
    const float* Wo = (const float*)d_in[4];
    float* out = (float*)d_out;

    float *Qp, *Kp, *Vp, *Cp;
    cudaGetSymbolAddress((void**)&Qp, g_Q);
    cudaGetSymbolAddress((void**)&Kp, g_K);
    cudaGetSymbolAddress((void**)&Vp, g_V);
    cudaGetSymbolAddress((void**)&Cp, g_Ctx);

    dim3 gemm_grid(D_MODEL / 128, MROWS / 128);   // (8, 32)
    sgemm_kernel<<<gemm_grid, 256>>>(X, Wq, Qp, MROWS, D_MODEL, D_MODEL);
    sgemm_kernel<<<gemm_grid, 256>>>(X, Wk, Kp, MROWS, D_MODEL, D_MODEL);
    sgemm_kernel<<<gemm_grid, 256>>>(X, Wv, Vp, MROWS, D_MODEL, D_MODEL);

    dim3 fa_grid(S_LEN / 64, NH, BATCH);          // (32, 16, 2)
    flash_kernel<<<fa_grid, 64>>>(Qp, Kp, Vp, Cp);

    sgemm_kernel<<<gemm_grid, 256>>>(Cp, Wo, out, MROWS, D_MODEL, D_MODEL);
}

// round 4
// speedup vs baseline: 1.2866x; 1.2866x over previous
#include <cuda_runtime.h>
#include <cstdint>

// Problem constants
#define BATCH   2
#define S_LEN   2048
#define D_MODEL 1024
#define NH      16
#define HD      64
#define MROWS   (BATCH * S_LEN)   // 4096

// Scratch (allocation-free rule: __device__ globals)
__device__ float g_Q[MROWS * D_MODEL];
__device__ float g_K[MROWS * D_MODEL];
__device__ float g_V[MROWS * D_MODEL];
__device__ float g_Ctx[MROWS * D_MODEL];
__device__ float g_WqT[D_MODEL * D_MODEL];
__device__ float g_WkT[D_MODEL * D_MODEL];
__device__ float g_WvT[D_MODEL * D_MODEL];
__device__ float g_WoT[D_MODEL * D_MODEL];

// ---------------------------------------------------------------------------
// Helpers
// ---------------------------------------------------------------------------
__device__ __forceinline__ uint32_t smem_u32(const void* p) {
    uint32_t a;
    asm("{ .reg .u64 t; cvta.to.shared.u64 t, %1; cvt.u32.u64 %0, t; }"
        : "=r"(a) : "l"(p));
    return a;
}
__device__ __forceinline__ uint32_t f2tf32(float f) {
    uint32_t r;
    asm("cvt.rna.tf32.f32 %0, %1;" : "=r"(r) : "f"(f));
    return r;
}

#define CP_ASYNC16(dst, src) \
    asm volatile("cp.async.cg.shared.global [%0], [%1], 16;" :: "r"(dst), "l"(src))
#define CP_COMMIT() asm volatile("cp.async.commit_group;" ::: "memory")
#define CP_WAIT0()  asm volatile("cp.async.wait_group 0;" ::: "memory")
#define CP_WAIT1()  asm volatile("cp.async.wait_group 1;" ::: "memory")

// mma.sync m16n8k8 tf32: D(16x8,f32) += A(16x8,tf32,row) * B(8x8,tf32,col)
#define MMA_TF32(d, a, b) \
    asm volatile( \
        "mma.sync.aligned.m16n8k8.row.col.f32.tf32.tf32.f32 " \
        "{%0,%1,%2,%3}, {%4,%5,%6,%7}, {%8,%9}, {%0,%1,%2,%3};" \
        : "+f"((d)[0]), "+f"((d)[1]), "+f"((d)[2]), "+f"((d)[3]) \
        : "r"((a)[0]), "r"((a)[1]), "r"((a)[2]), "r"((a)[3]), \
          "r"((b)[0]), "r"((b)[1]))

// ---------------------------------------------------------------------------
// tf32 tensor-core GEMM: C[M,1024] = A[M,1024] * Bt[1024,1024]^T
// Bt is the K-major transposed weight (Bt[n][k] = W[k][n]).
// CTA 128x128, 8 warps (4x2), warp tile 32x64, BK=32, cp.async double buffer.
// ---------------------------------------------------------------------------
#define GK   D_MODEL
#define BK   32
#define NST  (GK / BK)          // 32 stages
#define PAD  36                 // floats per smem row (32 + 4 pad)
#define TILE_F (128 * PAD)      // floats per tile
#define GEMM_SMEM (2 * 2 * TILE_F * 4)   // 73728 bytes

__global__ __launch_bounds__(256) void gemm_mma_kernel(
    const float* __restrict__ A, const float* __restrict__ Bt,
    float* __restrict__ C)
{
    extern __shared__ float sm[];
    const int tid  = threadIdx.x;
    const int lane = tid & 31;
    const int wid  = tid >> 5;
    const int wm   = wid & 3;          // warp row (4 x 32 rows)
    const int wn   = wid >> 2;         // warp col (2 x 64 cols)
    const int g    = lane >> 2;        // group 0..7
    const int tg   = lane & 3;         // thread-in-group 0..3
    const int m0   = blockIdx.y * 128;
    const int n0   = blockIdx.x * 128;

    const float* Ab = A  + (size_t)m0 * GK;
    const float* Bb = Bt + (size_t)n0 * GK;

    float acc[2][8][4];
#pragma unroll
    for (int mi = 0; mi < 2; mi++)
#pragma unroll
        for (int ni = 0; ni < 8; ni++)
#pragma unroll
            for (int r = 0; r < 4; r++) acc[mi][ni][r] = 0.f;

    // stage loader: 128x32 A tile + 128x32 B tile, 16B cp.async chunks
    auto load_stage = [&](int s) {
        float* dA = sm + (s & 1) * 2 * TILE_F;
        float* dB = dA + TILE_F;
        const float* Ak = Ab + s * BK;
        const float* Bk = Bb + s * BK;
#pragma unroll
        for (int i = 0; i < 4; i++) {
            const int c   = tid + i * 256;     // 0..1023
            const int row = c >> 3;            // 0..127
            const int ch  = c & 7;             // 16B chunk in row
            const uint32_t da = smem_u32(dA + row * PAD + ch * 4);
            const uint32_t db = smem_u32(dB + row * PAD + ch * 4);
            CP_ASYNC16(da, Ak + (size_t)row * GK + ch * 4);
            CP_ASYNC16(db, Bk + (size_t)row * GK + ch * 4);
        }
    };

    load_stage(0);
    CP_COMMIT();

    for (int s = 0; s < NST; s++) {
        if (s + 1 < NST) {
            load_stage(s + 1);
            CP_COMMIT();
            CP_WAIT1();
        } else {
            CP_WAIT0();
        }
        __syncthreads();

        const float* sA = sm + (s & 1) * 2 * TILE_F;
        const float* sB = sA + TILE_F;

#pragma unroll
        for (int kk = 0; kk < 4; kk++) {
            const int k0 = kk * 8;
            uint32_t a[2][4], b[8][2];
#pragma unroll
            for (int mi = 0; mi < 2; mi++) {
                const int r = wm * 32 + mi * 16;
                a[mi][0] = f2tf32(sA[(r + g)     * PAD + k0 + tg]);
                a[mi][1] = f2tf32(sA[(r + g + 8) * PAD + k0 + tg]);
                a[mi][2] = f2tf32(sA[(r + g)     * PAD + k0 + tg + 4]);
                a[mi][3] = f2tf32(sA[(r + g + 8) * PAD + k0 + tg + 4]);
            }
#pragma unroll
            for (int ni = 0; ni < 8; ni++) {
                const int cb = wn * 64 + ni * 8;
                b[ni][0] = f2tf32(sB[(cb + g) * PAD + k0 + tg]);
                b[ni][1] = f2tf32(sB[(cb + g) * PAD + k0 + tg + 4]);
            }
#pragma unroll
            for (int mi = 0; mi < 2; mi++)
#pragma unroll
                for (int ni = 0; ni < 8; ni++)
                    MMA_TF32(acc[mi][ni], a[mi], b[ni]);
        }
        __syncthreads();
    }

    // epilogue: D fragment (16x8) rows g / g+8, cols tg*2, tg*2+1
#pragma unroll
    for (int mi = 0; mi < 2; mi++) {
#pragma unroll
        for (int ni = 0; ni < 8; ni++) {
            const int r = m0 + wm * 32 + mi * 16 + g;
            const int c = n0 + wn * 64 + ni * 8 + tg * 2;
            *(float2*)&C[(size_t)r * D_MODEL + c] =
                make_float2(acc[mi][ni][0], acc[mi][ni][1]);
            *(float2*)&C[(size_t)(r + 8) * D_MODEL + c] =
                make_float2(acc[mi][ni][2], acc[mi][ni][3]);
        }
    }
}

// ---------------------------------------------------------------------------
// 1024x1024 fp32 transpose: out[n][k] = in[k][n]
// ---------------------------------------------------------------------------
__global__ __launch_bounds__(256) void transpose1024_kernel(
    const float* __restrict__ in, float* __restrict__ out)
{
    __shared__ float t[32][33];
    int x  = blockIdx.x * 32 + threadIdx.x;
    int y0 = blockIdx.y * 32 + threadIdx.y;
#pragma unroll
    for (int j = 0; j < 32; j += 8)
        t[threadIdx.y + j][threadIdx.x] = in[(size_t)(y0 + j) * D_MODEL + x];
    __syncthreads();
    x  = blockIdx.y * 32 + threadIdx.x;
    y0 = blockIdx.x * 32 + threadIdx.y;
#pragma unroll
    for (int j = 0; j < 32; j += 8)
        out[(size_t)(y0 + j) * D_MODEL + x] = t[threadIdx.x][threadIdx.y + j];
}

// ---------------------------------------------------------------------------
// Causal flash attention, fp32 (unchanged from passing R2 kernel).
// ---------------------------------------------------------------------------
__global__ __launch_bounds__(64) void flash_kernel(
    const float* __restrict__ Qg, const float* __restrict__ Kg,
    const float* __restrict__ Vg, float* __restrict__ Ctx)
{
    __shared__ float Ks[32][64];
    __shared__ float Vs[32][64];

    const int b  = blockIdx.z;
    const int h  = blockIdx.y;
    const int q0 = blockIdx.x * 64;
    const int t  = threadIdx.x;
    const int qi = q0 + t;

    const size_t head_off = (size_t)h * HD;
    const float* qptr = Qg + ((size_t)(b * S_LEN + qi)) * D_MODEL + head_off;

    float q[64], o[64];
#pragma unroll
    for (int d = 0; d < 64; d += 4) {
        float4 v = *(const float4*)(qptr + d);
        q[d] = v.x; q[d+1] = v.y; q[d+2] = v.z; q[d+3] = v.w;
    }
#pragma unroll
    for (int d = 0; d < 64; d++) o[d] = 0.f;

    float mrun = -1e30f, lrun = 0.f;
    const float scale = 0.125f;   // 1/sqrt(64)

    for (int k0 = 0; k0 < q0 + 64; k0 += 32) {
        const int krow = t >> 1;
        const int kcol = (t & 1) * 32;
        const float* kp = Kg + ((size_t)(b * S_LEN + k0 + krow)) * D_MODEL + head_off + kcol;
        const float* vp = Vg + ((size_t)(b * S_LEN + k0 + krow)) * D_MODEL + head_off + kcol;
        __syncthreads();
#pragma unroll
        for (int d = 0; d < 32; d += 4) {
            *(float4*)&Ks[krow][kcol + d] = *(const float4*)(kp + d);
            *(float4*)&Vs[krow][kcol + d] = *(const float4*)(vp + d);
        }
        __syncthreads();

        const bool needs_mask = (k0 + 31 > qi);
        float s[32];
        float mt = -1e30f;
#pragma unroll 4
        for (int j = 0; j < 32; j++) {
            const float4* k4 = (const float4*)Ks[j];
            float acc = 0.f;
#pragma unroll
            for (int d4 = 0; d4 < 16; d4++) {
                float4 kv = k4[d4];
                acc = fmaf(q[d4*4+0], kv.x, acc);
                acc = fmaf(q[d4*4+1], kv.y, acc);
                acc = fmaf(q[d4*4+2], kv.z, acc);
                acc = fmaf(q[d4*4+3], kv.w, acc);
            }
            acc *= scale;
            if (needs_mask && (k0 + j) > qi) acc = -1e30f;
            s[j] = acc;
            mt = fmaxf(mt, acc);
        }

        const float mnew  = fmaxf(mrun, mt);
        const float alpha = __expf(mrun - mnew);
        lrun *= alpha;
#pragma unroll
        for (int d = 0; d < 64; d++) o[d] *= alpha;

#pragma unroll 2
        for (int j = 0; j < 32; j++) {
            float p = __expf(s[j] - mnew);
            lrun += p;
            const float4* v4 = (const float4*)Vs[j];
#pragma unroll
            for (int d4 = 0; d4 < 16; d4++) {
                float4 vv = v4[d4];
                o[d4*4+0] = fmaf(p, vv.x, o[d4*4+0]);
                o[d4*4+1] = fmaf(p, vv.y, o[d4*4+1]);
                o[d4*4+2] = fmaf(p, vv.z, o[d4*4+2]);
                o[d4*4+3] = fmaf(p, vv.w, o[d4*4+3]);
            }
        }
        mrun = mnew;
    }

    const float inv = 1.f / lrun;
    float* op = Ctx + ((size_t)(b * S_LEN + qi)) * D_MODEL + head_off;
#pragma unroll
    for (int d = 0; d < 64; d += 4) {
        *(float4*)(op + d) = make_float4(o[d]*inv, o[d+1]*inv, o[d+2]*inv, o[d+3]*inv);
    }
}

// ---------------------------------------------------------------------------
extern "C" void kernel_launch(void* const* d_in, const int* in_sizes, int n_in,
                              void* d_out, int out_size)
{
    const float* X  = (const float*)d_in[0];
    const float* Wq = (const float*)d_in[1];
    const float* Wk = (const float*)d_in[2];
    const float* Wv = (const float*)d_in[3];
    const float* Wo = (const float*)d_in[4];
    float* out = (float*)d_out;

    float *Qp, *Kp, *Vp, *Cp, *WqT, *WkT, *WvT, *WoT;
    cudaGetSymbolAddress((void**)&Qp,  g_Q);
    cudaGetSymbolAddress((void**)&Kp,  g_K);
    cudaGetSymbolAddress((void**)&Vp,  g_V);
    cudaGetSymbolAddress((void**)&Cp,  g_Ctx);
    cudaGetSymbolAddress((void**)&WqT, g_WqT);
    cudaGetSymbolAddress((void**)&WkT, g_WkT);
    cudaGetSymbolAddress((void**)&WvT, g_WvT);
    cudaGetSymbolAddress((void**)&WoT, g_WoT);

    cudaFuncSetAttribute(gemm_mma_kernel,
                         cudaFuncAttributeMaxDynamicSharedMemorySize, GEMM_SMEM);

    dim3 tr_grid(32, 32), tr_blk(32, 8);
    transpose1024_kernel<<<tr_grid, tr_blk>>>(Wq, WqT);
    transpose1024_kernel<<<tr_grid, tr_blk>>>(Wk, WkT);
    transpose1024_kernel<<<tr_grid, tr_blk>>>(Wv, WvT);
    transpose1024_kernel<<<tr_grid, tr_blk>>>(Wo, WoT);

    dim3 gemm_grid(D_MODEL / 128, MROWS / 128);   // (8, 32)
    gemm_mma_kernel<<<gemm_grid, 256, GEMM_SMEM>>>(X, WqT, Qp);
    gemm_mma_kernel<<<gemm_grid, 256, GEMM_SMEM>>>(X, WkT, Kp);
    gemm_mma_kernel<<<gemm_grid, 256, GEMM_SMEM>>>(X, WvT, Vp);

    dim3 fa_grid(S_LEN / 64, NH, BATCH);          // (32, 16, 2)
    flash_kernel<<<fa_grid, 64>>>(Qp, Kp, Vp, Cp);

    gemm_mma_kernel<<<gemm_grid, 256, GEMM_SMEM>>>(Cp, WoT, out);
}

// round 5
// speedup vs baseline: 2.9957x; 2.3284x over previous
#include <cuda_runtime.h>
#include <cstdint>

// Problem constants
#define BATCH   2
#define S_LEN   2048
#define D_MODEL 1024
#define NH      16
#define HD      64
#define MROWS   (BATCH * S_LEN)   // 4096

// Scratch (allocation-free rule: __device__ globals)
__device__ float g_Q[MROWS * D_MODEL];
__device__ float g_K[MROWS * D_MODEL];
__device__ float g_V[MROWS * D_MODEL];
__device__ float g_Ctx[MROWS * D_MODEL];
__device__ float g_Xr[MROWS * D_MODEL];
__device__ float g_WqT[D_MODEL * D_MODEL];
__device__ float g_WkT[D_MODEL * D_MODEL];
__device__ float g_WvT[D_MODEL * D_MODEL];
__device__ float g_WoT[D_MODEL * D_MODEL];

// ---------------------------------------------------------------------------
// Helpers
// ---------------------------------------------------------------------------
__device__ __forceinline__ uint32_t smem_u32(const void* p) {
    uint32_t a;
    asm("{ .reg .u64 t; cvta.to.shared.u64 t, %1; cvt.u32.u64 %0, t; }"
        : "=r"(a) : "l"(p));
    return a;
}
// round-to-nearest tf32, returned as float bit pattern
__device__ __forceinline__ float tf32r(float f) {
    uint32_t r;
    asm("cvt.rna.tf32.f32 %0, %1;" : "=r"(r) : "f"(f));
    return __uint_as_float(r);
}

#define CP_ASYNC16(dst, src) \
    asm volatile("cp.async.cg.shared.global [%0], [%1], 16;" :: "r"(dst), "l"(src))
#define CP_COMMIT() asm volatile("cp.async.commit_group;" ::: "memory")
#define CP_WAIT0()  asm volatile("cp.async.wait_group 0;" ::: "memory")
#define CP_WAIT1()  asm volatile("cp.async.wait_group 1;" ::: "memory")

// mma.sync m16n8k8 tf32: D(16x8,f32) += A(16x8,tf32,row) * B(8x8,tf32,col)
#define MMA_TF32(d, a, b) \
    asm volatile( \
        "mma.sync.aligned.m16n8k8.row.col.f32.tf32.tf32.f32 " \
        "{%0,%1,%2,%3}, {%4,%5,%6,%7}, {%8,%9}, {%0,%1,%2,%3};" \
        : "+f"((d)[0]), "+f"((d)[1]), "+f"((d)[2]), "+f"((d)[3]) \
        : "r"((a)[0]), "r"((a)[1]), "r"((a)[2]), "r"((a)[3]), \
          "r"((b)[0]), "r"((b)[1]))

// ---------------------------------------------------------------------------
// tf32 tensor-core GEMM: C[M,1024] = A[M,1024] * Bt[1024,1024]^T
// Inputs pre-rounded to tf32; inner loop consumes raw bits (no cvt).
// CTA 128x128, 8 warps (4x2), warp tile 32x64, BK=32, cp.async double buffer.
// RND != 0: round outputs to tf32 (for tensors consumed as tf32 operands).
// ---------------------------------------------------------------------------
#define GK   D_MODEL
#define BK   32
#define NST  (GK / BK)          // 32 stages
#define PAD  36                 // floats per smem row (32 + 4 pad)
#define TILE_F (128 * PAD)
#define GEMM_SMEM (2 * 2 * TILE_F * 4)   // 73728 bytes

template <int RND>
__global__ __launch_bounds__(256) void gemm_mma_kernel(
    const float* __restrict__ A, const float* __restrict__ Bt,
    float* __restrict__ C)
{
    extern __shared__ float sm[];
    const int tid  = threadIdx.x;
    const int lane = tid & 31;
    const int wid  = tid >> 5;
    const int wm   = wid & 3;
    const int wn   = wid >> 2;
    const int g    = lane >> 2;
    const int tg   = lane & 3;
    const int m0   = blockIdx.y * 128;
    const int n0   = blockIdx.x * 128;

    const float* Ab = A  + (size_t)m0 * GK;
    const float* Bb = Bt + (size_t)n0 * GK;

    float acc[2][8][4];
#pragma unroll
    for (int mi = 0; mi < 2; mi++)
#pragma unroll
        for (int ni = 0; ni < 8; ni++)
#pragma unroll
            for (int r = 0; r < 4; r++) acc[mi][ni][r] = 0.f;

    auto load_stage = [&](int s) {
        float* dA = sm + (s & 1) * 2 * TILE_F;
        float* dB = dA + TILE_F;
        const float* Ak = Ab + s * BK;
        const float* Bk = Bb + s * BK;
#pragma unroll
        for (int i = 0; i < 4; i++) {
            const int c   = tid + i * 256;
            const int row = c >> 3;
            const int ch  = c & 7;
            CP_ASYNC16(smem_u32(dA + row * PAD + ch * 4), Ak + (size_t)row * GK + ch * 4);
            CP_ASYNC16(smem_u32(dB + row * PAD + ch * 4), Bk + (size_t)row * GK + ch * 4);
        }
    };

    load_stage(0);
    CP_COMMIT();

    for (int s = 0; s < NST; s++) {
        if (s + 1 < NST) { load_stage(s + 1); CP_COMMIT(); CP_WAIT1(); }
        else             { CP_WAIT0(); }
        __syncthreads();

        const float* sA = sm + (s & 1) * 2 * TILE_F;
        const float* sB = sA + TILE_F;

#pragma unroll
        for (int kk = 0; kk < 4; kk++) {
            const int k0 = kk * 8;
            uint32_t a[2][4], b[8][2];
#pragma unroll
            for (int mi = 0; mi < 2; mi++) {
                const int r = wm * 32 + mi * 16;
                a[mi][0] = __float_as_uint(sA[(r + g)     * PAD + k0 + tg]);
                a[mi][1] = __float_as_uint(sA[(r + g + 8) * PAD + k0 + tg]);
                a[mi][2] = __float_as_uint(sA[(r + g)     * PAD + k0 + tg + 4]);
                a[mi][3] = __float_as_uint(sA[(r + g + 8) * PAD + k0 + tg + 4]);
            }
#pragma unroll
            for (int ni = 0; ni < 8; ni++) {
                const int cb = wn * 64 + ni * 8;
                b[ni][0] = __float_as_uint(sB[(cb + g) * PAD + k0 + tg]);
                b[ni][1] = __float_as_uint(sB[(cb + g) * PAD + k0 + tg + 4]);
            }
#pragma unroll
            for (int mi = 0; mi < 2; mi++)
#pragma unroll
                for (int ni = 0; ni < 8; ni++)
                    MMA_TF32(acc[mi][ni], a[mi], b[ni]);
        }
        __syncthreads();
    }

#pragma unroll
    for (int mi = 0; mi < 2; mi++) {
#pragma unroll
        for (int ni = 0; ni < 8; ni++) {
            const int r = m0 + wm * 32 + mi * 16 + g;
            const int c = n0 + wn * 64 + ni * 8 + tg * 2;
            float v0 = acc[mi][ni][0], v1 = acc[mi][ni][1];
            float v2 = acc[mi][ni][2], v3 = acc[mi][ni][3];
            if (RND) { v0 = tf32r(v0); v1 = tf32r(v1); v2 = tf32r(v2); v3 = tf32r(v3); }
            *(float2*)&C[(size_t)r * D_MODEL + c]       = make_float2(v0, v1);
            *(float2*)&C[(size_t)(r + 8) * D_MODEL + c] = make_float2(v2, v3);
        }
    }
}

// ---------------------------------------------------------------------------
// 1024x1024 transpose with tf32 rounding: out[n][k] = tf32(in[k][n])
// ---------------------------------------------------------------------------
__global__ __launch_bounds__(256) void transpose1024_kernel(
    const float* __restrict__ in, float* __restrict__ out)
{
    __shared__ float t[32][33];
    int x  = blockIdx.x * 32 + threadIdx.x;
    int y0 = blockIdx.y * 32 + threadIdx.y;
#pragma unroll
    for (int j = 0; j < 32; j += 8)
        t[threadIdx.y + j][threadIdx.x] = in[(size_t)(y0 + j) * D_MODEL + x];
    __syncthreads();
    x  = blockIdx.y * 32 + threadIdx.x;
    y0 = blockIdx.x * 32 + threadIdx.y;
#pragma unroll
    for (int j = 0; j < 32; j += 8)
        out[(size_t)(y0 + j) * D_MODEL + x] = tf32r(t[threadIdx.x][threadIdx.y + j]);
}

// elementwise tf32 rounding: out[i] = tf32(in[i])
__global__ __launch_bounds__(256) void round_kernel(
    const float* __restrict__ in, float* __restrict__ out, int n4)
{
    int i = blockIdx.x * blockDim.x + threadIdx.x;
    if (i < n4) {
        float4 v = ((const float4*)in)[i];
        ((float4*)out)[i] = make_float4(tf32r(v.x), tf32r(v.y), tf32r(v.z), tf32r(v.w));
    }
}

// ---------------------------------------------------------------------------
// Tensor-core causal flash attention (tf32 mma).
// Block = 64 q rows of one (b,h); 128 threads = 4 warps x 16 q rows.
// S = Q*K^T via m16n8k8 (Ks[key][d] = proven B layout); online softmax on
// C-fragments; P staged through warp-private smem; O += P*V with V transposed.
// All inputs pre-rounded tf32.
// ---------------------------------------------------------------------------
#define FPAD 68
#define FA_SMEM ((3 * 64 + 4 * 16) * FPAD * 4)   // 69632 bytes

__global__ __launch_bounds__(128) void flash_mma_kernel(
    const float* __restrict__ Qg, const float* __restrict__ Kg,
    const float* __restrict__ Vg, float* __restrict__ Ctx)
{
    extern __shared__ float fsm[];
    float* Qs = fsm;                    // [64][FPAD]
    float* Ks = Qs + 64 * FPAD;         // [64][FPAD]  (key-major, d cols)
    float* Vt = Ks + 64 * FPAD;         // [64][FPAD]  (d-major, key cols)
    float* Pb = Vt + 64 * FPAD;         // 4 x [16][FPAD]

    const int tid  = threadIdx.x;
    const int lane = tid & 31;
    const int wid  = tid >> 5;
    const int g    = lane >> 2;
    const int tg   = lane & 3;
    const int b    = blockIdx.z;
    const int h    = blockIdx.y;
    const int q0   = blockIdx.x * 64;

    const size_t hoff = (size_t)h * HD;
    const int lrow = tid >> 1;            // 0..63
    const int lcol = (tid & 1) * 32;      // 0 or 32

    // load Q tile (pre-rounded tf32)
    {
        const float* qp = Qg + ((size_t)(b * S_LEN + q0 + lrow)) * D_MODEL + hoff + lcol;
#pragma unroll
        for (int c = 0; c < 32; c += 4)
            *(float4*)&Qs[lrow * FPAD + lcol + c] = *(const float4*)(qp + c);
    }

    float o[8][4];
#pragma unroll
    for (int d = 0; d < 8; d++)
#pragma unroll
        for (int r = 0; r < 4; r++) o[d][r] = 0.f;
    float mrun[2] = {-1e30f, -1e30f};
    float lrun[2] = {0.f, 0.f};

    float* Pw = Pb + wid * 16 * FPAD;
    const int qrow_lo = q0 + wid * 16 + g;       // global q row for regs 0,1

    for (int k0 = 0; k0 <= q0; k0 += 64) {
        __syncthreads();
        // load K tile [key][d] and V tile transposed [d][key]
        {
            const float* kp = Kg + ((size_t)(b * S_LEN + k0 + lrow)) * D_MODEL + hoff + lcol;
            const float* vp = Vg + ((size_t)(b * S_LEN + k0 + lrow)) * D_MODEL + hoff + lcol;
#pragma unroll
            for (int c = 0; c < 32; c += 4) {
                *(float4*)&Ks[lrow * FPAD + lcol + c] = *(const float4*)(kp + c);
                float4 v = *(const float4*)(vp + c);
                Vt[(lcol + c + 0) * FPAD + lrow] = v.x;
                Vt[(lcol + c + 1) * FPAD + lrow] = v.y;
                Vt[(lcol + c + 2) * FPAD + lrow] = v.z;
                Vt[(lcol + c + 3) * FPAD + lrow] = v.w;
            }
        }
        __syncthreads();

        // ---- S = Q * K^T ----
        float sf[8][4];
#pragma unroll
        for (int nb = 0; nb < 8; nb++)
#pragma unroll
            for (int r = 0; r < 4; r++) sf[nb][r] = 0.f;

#pragma unroll
        for (int kk = 0; kk < 8; kk++) {
            const int kd = kk * 8;
            uint32_t a[4];
            const int ar = wid * 16 + g;
            a[0] = __float_as_uint(Qs[(ar)     * FPAD + kd + tg]);
            a[1] = __float_as_uint(Qs[(ar + 8) * FPAD + kd + tg]);
            a[2] = __float_as_uint(Qs[(ar)     * FPAD + kd + tg + 4]);
            a[3] = __float_as_uint(Qs[(ar + 8) * FPAD + kd + tg + 4]);
#pragma unroll
            for (int nb = 0; nb < 8; nb++) {
                uint32_t bfr[2];
                bfr[0] = __float_as_uint(Ks[(nb * 8 + g) * FPAD + kd + tg]);
                bfr[1] = __float_as_uint(Ks[(nb * 8 + g) * FPAD + kd + tg + 4]);
                MMA_TF32(sf[nb], a, bfr);
            }
        }

        // ---- scale + causal mask (diagonal tile only) ----
        const bool diag = (k0 == q0);
#pragma unroll
        for (int nb = 0; nb < 8; nb++) {
#pragma unroll
            for (int r = 0; r < 4; r++) {
                float s = sf[nb][r] * 0.125f;
                if (diag) {
                    const int kcol = k0 + nb * 8 + tg * 2 + (r & 1);
                    const int qrow = qrow_lo + (r >> 1) * 8;
                    if (kcol > qrow) s = -1e30f;
                }
                sf[nb][r] = s;
            }
        }

        // ---- online softmax (rows g and g+8) ----
#pragma unroll
        for (int r = 0; r < 2; r++) {
            float mt = -1e30f;
#pragma unroll
            for (int nb = 0; nb < 8; nb++)
                mt = fmaxf(mt, fmaxf(sf[nb][r * 2], sf[nb][r * 2 + 1]));
            mt = fmaxf(mt, __shfl_xor_sync(0xFFFFFFFFu, mt, 1));
            mt = fmaxf(mt, __shfl_xor_sync(0xFFFFFFFFu, mt, 2));
            const float mnew  = fmaxf(mrun[r], mt);
            const float alpha = __expf(mrun[r] - mnew);
            float ls = 0.f;
#pragma unroll
            for (int nb = 0; nb < 8; nb++) {
                float p0 = __expf(sf[nb][r * 2]     - mnew);
                float p1 = __expf(sf[nb][r * 2 + 1] - mnew);
                ls += p0 + p1;
                sf[nb][r * 2]     = p0;
                sf[nb][r * 2 + 1] = p1;
            }
            ls += __shfl_xor_sync(0xFFFFFFFFu, ls, 1);
            ls += __shfl_xor_sync(0xFFFFFFFFu, ls, 2);
            lrun[r] = lrun[r] * alpha + ls;
            mrun[r] = mnew;
#pragma unroll
            for (int d = 0; d < 8; d++) {
                o[d][r * 2]     *= alpha;
                o[d][r * 2 + 1] *= alpha;
            }
        }

        // ---- stage P (rounded tf32) into warp-private smem ----
#pragma unroll
        for (int nb = 0; nb < 8; nb++) {
            *(float2*)&Pw[g * FPAD + nb * 8 + tg * 2] =
                make_float2(tf32r(sf[nb][0]), tf32r(sf[nb][1]));
            *(float2*)&Pw[(g + 8) * FPAD + nb * 8 + tg * 2] =
                make_float2(tf32r(sf[nb][2]), tf32r(sf[nb][3]));
        }
        __syncwarp();

        // ---- O += P * V ----
#pragma unroll
        for (int kk = 0; kk < 8; kk++) {
            const int kd = kk * 8;
            uint32_t a[4];
            a[0] = __float_as_uint(Pw[(g)     * FPAD + kd + tg]);
            a[1] = __float_as_uint(Pw[(g + 8) * FPAD + kd + tg]);
            a[2] = __float_as_uint(Pw[(g)     * FPAD + kd + tg + 4]);
            a[3] = __float_as_uint(Pw[(g + 8) * FPAD + kd + tg + 4]);
#pragma unroll
            for (int db = 0; db < 8; db++) {
                uint32_t bfr[2];
                bfr[0] = __float_as_uint(Vt[(db * 8 + g) * FPAD + kd + tg]);
                bfr[1] = __float_as_uint(Vt[(db * 8 + g) * FPAD + kd + tg + 4]);
                MMA_TF32(o[db], a, bfr);
            }
        }
        __syncwarp();   // Pw reused next iteration
    }

    // ---- epilogue: normalize, round to tf32, store ----
    const float inv0 = 1.f / lrun[0];
    const float inv1 = 1.f / lrun[1];
    float* c0 = Ctx + ((size_t)(b * S_LEN + qrow_lo)) * D_MODEL + hoff;
    float* c1 = c0 + 8 * D_MODEL;
#pragma unroll
    for (int db = 0; db < 8; db++) {
        const int c = db * 8 + tg * 2;
        *(float2*)(c0 + c) = make_float2(tf32r(o[db][0] * inv0), tf32r(o[db][1] * inv0));
        *(float2*)(c1 + c) = make_float2(tf32r(o[db][2] * inv1), tf32r(o[db][3] * inv1));
    }
}

// ---------------------------------------------------------------------------
extern "C" void kernel_launch(void* const* d_in, const int* in_sizes, int n_in,
                              void* d_out, int out_size)
{
    const float* X  = (const float*)d_in[0];
    const float* Wq = (const float*)d_in[1];
    const float* Wk = (const float*)d_in[2];
    const float* Wv = (const float*)d_in[3];
    const float* Wo = (const float*)d_in[4];
    float* out = (float*)d_out;

    float *Qp, *Kp, *Vp, *Cp, *Xr, *WqT, *WkT, *WvT, *WoT;
    cudaGetSymbolAddress((void**)&Qp,  g_Q);
    cudaGetSymbolAddress((void**)&Kp,  g_K);
    cudaGetSymbolAddress((void**)&Vp,  g_V);
    cudaGetSymbolAddress((void**)&Cp,  g_Ctx);
    cudaGetSymbolAddress((void**)&Xr,  g_Xr);
    cudaGetSymbolAddress((void**)&WqT, g_WqT);
    cudaGetSymbolAddress((void**)&WkT, g_WkT);
    cudaGetSymbolAddress((void**)&WvT, g_WvT);
    cudaGetSymbolAddress((void**)&WoT, g_WoT);

    cudaFuncSetAttribute(gemm_mma_kernel<0>,
                         cudaFuncAttributeMaxDynamicSharedMemorySize, GEMM_SMEM);
    cudaFuncSetAttribute(gemm_mma_kernel<1>,
                         cudaFuncAttributeMaxDynamicSharedMemorySize, GEMM_SMEM);
    cudaFuncSetAttribute(flash_mma_kernel,
                         cudaFuncAttributeMaxDynamicSharedMemorySize, FA_SMEM);

    // pre-round X; transpose+round weights
    round_kernel<<<(MROWS * D_MODEL / 4 + 255) / 256, 256>>>(X, Xr, MROWS * D_MODEL / 4);
    dim3 tr_grid(32, 32), tr_blk(32, 8);
    transpose1024_kernel<<<tr_grid, tr_blk>>>(Wq, WqT);
    transpose1024_kernel<<<tr_grid, tr_blk>>>(Wk, WkT);
    transpose1024_kernel<<<tr_grid, tr_blk>>>(Wv, WvT);
    transpose1024_kernel<<<tr_grid, tr_blk>>>(Wo, WoT);

    dim3 gemm_grid(D_MODEL / 128, MROWS / 128);   // (8, 32)
    gemm_mma_kernel<1><<<gemm_grid, 256, GEMM_SMEM>>>(Xr, WqT, Qp);
    gemm_mma_kernel<1><<<gemm_grid, 256, GEMM_SMEM>>>(Xr, WkT, Kp);
    gemm_mma_kernel<1><<<gemm_grid, 256, GEMM_SMEM>>>(Xr, WvT, Vp);

    dim3 fa_grid(S_LEN / 64, NH, BATCH);          // (32, 16, 2)
    flash_mma_kernel<<<fa_grid, 128, FA_SMEM>>>(Qp, Kp, Vp, Cp);

    gemm_mma_kernel<0><<<gemm_grid, 256, GEMM_SMEM>>>(Cp, WoT, out);
}

// round 6
// speedup vs baseline: 4.1079x; 1.3713x over previous
#include <cuda_runtime.h>
#include <cstdint>

// Problem constants
#define BATCH   2
#define S_LEN   2048
#define D_MODEL 1024
#define NH      16
#define HD      64
#define MROWS   (BATCH * S_LEN)   // 4096

// Scratch (allocation-free rule: __device__ globals)
__device__ float g_Q[MROWS * D_MODEL];
__device__ float g_K[MROWS * D_MODEL];
__device__ float g_V[MROWS * D_MODEL];
__device__ float g_Ctx[MROWS * D_MODEL];
__device__ float g_Xr[MROWS * D_MODEL];
__device__ float g_WT[3 * D_MODEL * D_MODEL];   // WqT | WkT | WvT
__device__ float g_WoT[D_MODEL * D_MODEL];

// ---------------------------------------------------------------------------
// Helpers
// ---------------------------------------------------------------------------
__device__ __forceinline__ uint32_t smem_u32(const void* p) {
    uint32_t a;
    asm("{ .reg .u64 t; cvta.to.shared.u64 t, %1; cvt.u32.u64 %0, t; }"
        : "=r"(a) : "l"(p));
    return a;
}
__device__ __forceinline__ float tf32r(float f) {
    uint32_t r;
    asm("cvt.rna.tf32.f32 %0, %1;" : "=r"(r) : "f"(f));
    return __uint_as_float(r);
}

#define CP_ASYNC16(dst, src) \
    asm volatile("cp.async.cg.shared.global [%0], [%1], 16;" :: "r"(dst), "l"(src))
#define CP_COMMIT() asm volatile("cp.async.commit_group;" ::: "memory")
#define CP_WAIT0()  asm volatile("cp.async.wait_group 0;" ::: "memory")
#define CP_WAIT1()  asm volatile("cp.async.wait_group 1;" ::: "memory")

// mma.sync m16n8k8 tf32
#define MMA_TF32(d, a, b) \
    asm volatile( \
        "mma.sync.aligned.m16n8k8.row.col.f32.tf32.tf32.f32 " \
        "{%0,%1,%2,%3}, {%4,%5,%6,%7}, {%8,%9}, {%0,%1,%2,%3};" \
        : "+f"((d)[0]), "+f"((d)[1]), "+f"((d)[2]), "+f"((d)[3]) \
        : "r"((a)[0]), "r"((a)[1]), "r"((a)[2]), "r"((a)[3]), \
          "r"((b)[0]), "r"((b)[1]))

// ---------------------------------------------------------------------------
// tf32 tensor-core GEMM.  QKV mode: C chosen from {Q,K,V} by n-block.
// CTA 128x128, 8 warps (4x2), warp tile 32x64, BK=32, cp.async double buffer.
// ---------------------------------------------------------------------------
#define GK   D_MODEL
#define BK   32
#define NST  (GK / BK)          // 32 stages
#define PAD  36
#define TILE_F (128 * PAD)
#define GEMM_SMEM (2 * 2 * TILE_F * 4)   // 73728 bytes

// QKV: if C1 != nullptr, blockIdx.x in [0,24): n-blocks 0-7 -> C0, 8-15 -> C1,
// 16-23 -> C2, weight slice selected accordingly. RND: round output to tf32.
template <int RND>
__global__ __launch_bounds__(256) void gemm_mma_kernel(
    const float* __restrict__ A, const float* __restrict__ Bt,
    float* __restrict__ C0, float* __restrict__ C1, float* __restrict__ C2)
{
    extern __shared__ float sm[];
    const int tid  = threadIdx.x;
    const int lane = tid & 31;
    const int wid  = tid >> 5;
    const int wm   = wid & 3;
    const int wn   = wid >> 2;
    const int g    = lane >> 2;
    const int tg   = lane & 3;
    const int m0   = blockIdx.y * 128;

    float* C = C0;
    const float* Bbase = Bt;
    int n0;
    if (C1) {
        const int which = blockIdx.x >> 3;
        C = (which == 0) ? C0 : (which == 1) ? C1 : C2;
        Bbase = Bt + (size_t)which * D_MODEL * D_MODEL;
        n0 = (blockIdx.x & 7) * 128;
    } else {
        n0 = blockIdx.x * 128;
    }

    const float* Ab = A     + (size_t)m0 * GK;
    const float* Bb = Bbase + (size_t)n0 * GK;

    float acc[2][8][4];
#pragma unroll
    for (int mi = 0; mi < 2; mi++)
#pragma unroll
        for (int ni = 0; ni < 8; ni++)
#pragma unroll
            for (int r = 0; r < 4; r++) acc[mi][ni][r] = 0.f;

    auto load_stage = [&](int s) {
        float* dA = sm + (s & 1) * 2 * TILE_F;
        float* dB = dA + TILE_F;
        const float* Ak = Ab + s * BK;
        const float* Bk = Bb + s * BK;
#pragma unroll
        for (int i = 0; i < 4; i++) {
            const int c   = tid + i * 256;
            const int row = c >> 3;
            const int ch  = c & 7;
            CP_ASYNC16(smem_u32(dA + row * PAD + ch * 4), Ak + (size_t)row * GK + ch * 4);
            CP_ASYNC16(smem_u32(dB + row * PAD + ch * 4), Bk + (size_t)row * GK + ch * 4);
        }
    };

    load_stage(0);
    CP_COMMIT();

    for (int s = 0; s < NST; s++) {
        if (s + 1 < NST) { load_stage(s + 1); CP_COMMIT(); CP_WAIT1(); }
        else             { CP_WAIT0(); }
        __syncthreads();

        const float* sA = sm + (s & 1) * 2 * TILE_F;
        const float* sB = sA + TILE_F;

#pragma unroll
        for (int kk = 0; kk < 4; kk++) {
            const int k0 = kk * 8;
            uint32_t a[2][4], b[8][2];
#pragma unroll
            for (int mi = 0; mi < 2; mi++) {
                const int r = wm * 32 + mi * 16;
                a[mi][0] = __float_as_uint(sA[(r + g)     * PAD + k0 + tg]);
                a[mi][1] = __float_as_uint(sA[(r + g + 8) * PAD + k0 + tg]);
                a[mi][2] = __float_as_uint(sA[(r + g)     * PAD + k0 + tg + 4]);
                a[mi][3] = __float_as_uint(sA[(r + g + 8) * PAD + k0 + tg + 4]);
            }
#pragma unroll
            for (int ni = 0; ni < 8; ni++) {
                const int cb = wn * 64 + ni * 8;
                b[ni][0] = __float_as_uint(sB[(cb + g) * PAD + k0 + tg]);
                b[ni][1] = __float_as_uint(sB[(cb + g) * PAD + k0 + tg + 4]);
            }
#pragma unroll
            for (int mi = 0; mi < 2; mi++)
#pragma unroll
                for (int ni = 0; ni < 8; ni++)
                    MMA_TF32(acc[mi][ni], a[mi], b[ni]);
        }
        __syncthreads();
    }

#pragma unroll
    for (int mi = 0; mi < 2; mi++) {
#pragma unroll
        for (int ni = 0; ni < 8; ni++) {
            const int r = m0 + wm * 32 + mi * 16 + g;
            const int c = n0 + wn * 64 + ni * 8 + tg * 2;
            float v0 = acc[mi][ni][0], v1 = acc[mi][ni][1];
            float v2 = acc[mi][ni][2], v3 = acc[mi][ni][3];
            if (RND) { v0 = tf32r(v0); v1 = tf32r(v1); v2 = tf32r(v2); v3 = tf32r(v3); }
            *(float2*)&C[(size_t)r * D_MODEL + c]       = make_float2(v0, v1);
            *(float2*)&C[(size_t)(r + 8) * D_MODEL + c] = make_float2(v2, v3);
        }
    }
}

// ---------------------------------------------------------------------------
// Batched 1024x1024 transpose with tf32 rounding; z selects which weight.
// z<3 -> g_WT slice z; z==3 -> WoT.
// ---------------------------------------------------------------------------
__global__ __launch_bounds__(256) void transpose4_kernel(
    const float* __restrict__ w0, const float* __restrict__ w1,
    const float* __restrict__ w2, const float* __restrict__ w3,
    float* __restrict__ wt, float* __restrict__ wot)
{
    __shared__ float t[32][33];
    const int z = blockIdx.z;
    const float* in = (z == 0) ? w0 : (z == 1) ? w1 : (z == 2) ? w2 : w3;
    float* out = (z < 3) ? (wt + (size_t)z * D_MODEL * D_MODEL) : wot;

    int x  = blockIdx.x * 32 + threadIdx.x;
    int y0 = blockIdx.y * 32 + threadIdx.y;
#pragma unroll
    for (int j = 0; j < 32; j += 8)
        t[threadIdx.y + j][threadIdx.x] = in[(size_t)(y0 + j) * D_MODEL + x];
    __syncthreads();
    x  = blockIdx.y * 32 + threadIdx.x;
    y0 = blockIdx.x * 32 + threadIdx.y;
#pragma unroll
    for (int j = 0; j < 32; j += 8)
        out[(size_t)(y0 + j) * D_MODEL + x] = tf32r(t[threadIdx.x][threadIdx.y + j]);
}

// elementwise tf32 rounding
__global__ __launch_bounds__(256) void round_kernel(
    const float* __restrict__ in, float* __restrict__ out, int n4)
{
    int i = blockIdx.x * blockDim.x + threadIdx.x;
    if (i < n4) {
        float4 v = ((const float4*)in)[i];
        ((float4*)out)[i] = make_float4(tf32r(v.x), tf32r(v.y), tf32r(v.z), tf32r(v.w));
    }
}

// ---------------------------------------------------------------------------
// Tensor-core causal flash attention (tf32 mma), cp.async double-buffered K/V.
// Block = 64 q rows of one (b,h); 128 threads = 4 warps x 16 q rows.
// K and V both stored row-major [key][d] in smem; PV B-fragments read V
// directly (no transpose). q-tiles processed in reverse launch order.
// ---------------------------------------------------------------------------
#define FPAD 68
// Qs[64] + Ks[2][64] + Vs[2][64] + Pb[4][16] rows of FPAD floats
#define FA_SMEM ((64 + 128 + 128 + 64) * FPAD * 4)   // 104448 bytes

__global__ __launch_bounds__(128) void flash_mma_kernel(
    const float* __restrict__ Qg, const float* __restrict__ Kg,
    const float* __restrict__ Vg, float* __restrict__ Ctx)
{
    extern __shared__ float fsm[];
    float* Qs  = fsm;                      // [64][FPAD]
    float* Ksb = Qs + 64 * FPAD;           // 2 x [64][FPAD]
    float* Vsb = Ksb + 2 * 64 * FPAD;      // 2 x [64][FPAD]
    float* Pb  = Vsb + 2 * 64 * FPAD;      // 4 x [16][FPAD]

    const int tid  = threadIdx.x;
    const int lane = tid & 31;
    const int wid  = tid >> 5;
    const int g    = lane >> 2;
    const int tg   = lane & 3;
    const int b    = blockIdx.z;
    const int h    = blockIdx.y;
    const int q0   = (gridDim.x - 1 - blockIdx.x) * 64;   // heavy tiles first

    const size_t hoff = (size_t)h * HD;
    const int lrow = tid >> 1;
    const int lcol = (tid & 1) * 32;

    const float* Kb = Kg + (size_t)b * S_LEN * D_MODEL + hoff;
    const float* Vb = Vg + (size_t)b * S_LEN * D_MODEL + hoff;

    // prefetch one K/V tile (64 keys) into buffer buf
    auto prefetch = [&](int k0, int buf) {
        float* dK = Ksb + buf * 64 * FPAD;
        float* dV = Vsb + buf * 64 * FPAD;
#pragma unroll
        for (int i = 0; i < 8; i++) {
            const int c   = tid + i * 128;   // 0..1023 (16B chunks)
            const int row = c >> 4;          // 0..63
            const int ch  = c & 15;          // 16B chunk in 64-float row
            const size_t go = (size_t)(k0 + row) * D_MODEL + ch * 4;
            CP_ASYNC16(smem_u32(dK + row * FPAD + ch * 4), Kb + go);
            CP_ASYNC16(smem_u32(dV + row * FPAD + ch * 4), Vb + go);
        }
    };

    // load Q tile
    {
        const float* qp = Qg + ((size_t)(b * S_LEN + q0 + lrow)) * D_MODEL + hoff + lcol;
#pragma unroll
        for (int c = 0; c < 32; c += 4)
            *(float4*)&Qs[lrow * FPAD + lcol + c] = *(const float4*)(qp + c);
    }

    float o[8][4];
#pragma unroll
    for (int d = 0; d < 8; d++)
#pragma unroll
        for (int r = 0; r < 4; r++) o[d][r] = 0.f;
    float mrun[2] = {-1e30f, -1e30f};
    float lrun[2] = {0.f, 0.f};

    float* Pw = Pb + wid * 16 * FPAD;
    const int qrow_lo = q0 + wid * 16 + g;
    const int ntiles  = q0 / 64 + 1;

    prefetch(0, 0);
    CP_COMMIT();

    for (int t = 0; t < ntiles; t++) {
        const int k0  = t * 64;
        const int buf = t & 1;
        if (t + 1 < ntiles) { prefetch((t + 1) * 64, buf ^ 1); CP_COMMIT(); CP_WAIT1(); }
        else                { CP_WAIT0(); }
        __syncthreads();

        const float* Ks = Ksb + buf * 64 * FPAD;
        const float* Vs = Vsb + buf * 64 * FPAD;

        // ---- S = Q * K^T ----
        float sf[8][4];
#pragma unroll
        for (int nb = 0; nb < 8; nb++)
#pragma unroll
            for (int r = 0; r < 4; r++) sf[nb][r] = 0.f;

#pragma unroll
        for (int kk = 0; kk < 8; kk++) {
            const int kd = kk * 8;
            uint32_t a[4];
            const int ar = wid * 16 + g;
            a[0] = __float_as_uint(Qs[(ar)     * FPAD + kd + tg]);
            a[1] = __float_as_uint(Qs[(ar + 8) * FPAD + kd + tg]);
            a[2] = __float_as_uint(Qs[(ar)     * FPAD + kd + tg + 4]);
            a[3] = __float_as_uint(Qs[(ar + 8) * FPAD + kd + tg + 4]);
#pragma unroll
            for (int nb = 0; nb < 8; nb++) {
                uint32_t bfr[2];
                bfr[0] = __float_as_uint(Ks[(nb * 8 + g) * FPAD + kd + tg]);
                bfr[1] = __float_as_uint(Ks[(nb * 8 + g) * FPAD + kd + tg + 4]);
                MMA_TF32(sf[nb], a, bfr);
            }
        }

        // ---- scale + causal mask (diagonal tile only) ----
        const bool diag = (k0 == q0);
#pragma unroll
        for (int nb = 0; nb < 8; nb++) {
#pragma unroll
            for (int r = 0; r < 4; r++) {
                float s = sf[nb][r] * 0.125f;
                if (diag) {
                    const int kcol = k0 + nb * 8 + tg * 2 + (r & 1);
                    const int qrow = qrow_lo + (r >> 1) * 8;
                    if (kcol > qrow) s = -1e30f;
                }
                sf[nb][r] = s;
            }
        }

        // ---- online softmax (rows g and g+8) ----
#pragma unroll
        for (int r = 0; r < 2; r++) {
            float mt = -1e30f;
#pragma unroll
            for (int nb = 0; nb < 8; nb++)
                mt = fmaxf(mt, fmaxf(sf[nb][r * 2], sf[nb][r * 2 + 1]));
            mt = fmaxf(mt, __shfl_xor_sync(0xFFFFFFFFu, mt, 1));
            mt = fmaxf(mt, __shfl_xor_sync(0xFFFFFFFFu, mt, 2));
            const float mnew  = fmaxf(mrun[r], mt);
            const float alpha = __expf(mrun[r] - mnew);
            float ls = 0.f;
#pragma unroll
            for (int nb = 0; nb < 8; nb++) {
                float p0 = __expf(sf[nb][r * 2]     - mnew);
                float p1 = __expf(sf[nb][r * 2 + 1] - mnew);
                ls += p0 + p1;
                sf[nb][r * 2]     = p0;
                sf[nb][r * 2 + 1] = p1;
            }
            ls += __shfl_xor_sync(0xFFFFFFFFu, ls, 1);
            ls += __shfl_xor_sync(0xFFFFFFFFu, ls, 2);
            lrun[r] = lrun[r] * alpha + ls;
            mrun[r] = mnew;
#pragma unroll
            for (int d = 0; d < 8; d++) {
                o[d][r * 2]     *= alpha;
                o[d][r * 2 + 1] *= alpha;
            }
        }

        // ---- stage P (rounded tf32) into warp-private smem ----
#pragma unroll
        for (int nb = 0; nb < 8; nb++) {
            *(float2*)&Pw[g * FPAD + nb * 8 + tg * 2] =
                make_float2(tf32r(sf[nb][0]), tf32r(sf[nb][1]));
            *(float2*)&Pw[(g + 8) * FPAD + nb * 8 + tg * 2] =
                make_float2(tf32r(sf[nb][2]), tf32r(sf[nb][3]));
        }
        __syncwarp();

        // ---- O += P * V  (B-fragments straight from row-major Vs) ----
#pragma unroll
        for (int kk = 0; kk < 8; kk++) {
            const int kd = kk * 8;
            uint32_t a[4];
            a[0] = __float_as_uint(Pw[(g)     * FPAD + kd + tg]);
            a[1] = __float_as_uint(Pw[(g + 8) * FPAD + kd + tg]);
            a[2] = __float_as_uint(Pw[(g)     * FPAD + kd + tg + 4]);
            a[3] = __float_as_uint(Pw[(g + 8) * FPAD + kd + tg + 4]);
#pragma unroll
            for (int db = 0; db < 8; db++) {
                uint32_t bfr[2];
                bfr[0] = __float_as_uint(Vs[(kd + tg)     * FPAD + db * 8 + g]);
                bfr[1] = __float_as_uint(Vs[(kd + tg + 4) * FPAD + db * 8 + g]);
                MMA_TF32(o[db], a, bfr);
            }
        }
        __syncthreads();   // all warps done with buf before it is overwritten
    }

    // ---- epilogue: normalize, round to tf32, store ----
    const float inv0 = 1.f / lrun[0];
    const float inv1 = 1.f / lrun[1];
    float* c0 = Ctx + ((size_t)(b * S_LEN + qrow_lo)) * D_MODEL + hoff;
    float* c1 = c0 + 8 * D_MODEL;
#pragma unroll
    for (int db = 0; db < 8; db++) {
        const int c = db * 8 + tg * 2;
        *(float2*)(c0 + c) = make_float2(tf32r(o[db][0] * inv0), tf32r(o[db][1] * inv0));
        *(float2*)(c1 + c) = make_float2(tf32r(o[db][2] * inv1), tf32r(o[db][3] * inv1));
    }
}

// ---------------------------------------------------------------------------
extern "C" void kernel_launch(void* const* d_in, const int* in_sizes, int n_in,
                              void* d_out, int out_size)
{
    const float* X  = (const float*)d_in[0];
    const float* Wq = (const float*)d_in[1];
    const float* Wk = (const float*)d_in[2];
    const float* Wv = (const float*)d_in[3];
    const float* Wo = (const float*)d_in[4];
    float* out = (float*)d_out;

    float *Qp, *Kp, *Vp, *Cp, *Xr, *WT, *WoT;
    cudaGetSymbolAddress((void**)&Qp,  g_Q);
    cudaGetSymbolAddress((void**)&Kp,  g_K);
    cudaGetSymbolAddress((void**)&Vp,  g_V);
    cudaGetSymbolAddress((void**)&Cp,  g_Ctx);
    cudaGetSymbolAddress((void**)&Xr,  g_Xr);
    cudaGetSymbolAddress((void**)&WT,  g_WT);
    cudaGetSymbolAddress((void**)&WoT, g_WoT);

    cudaFuncSetAttribute(gemm_mma_kernel<0>,
                         cudaFuncAttributeMaxDynamicSharedMemorySize, GEMM_SMEM);
    cudaFuncSetAttribute(gemm_mma_kernel<1>,
                         cudaFuncAttributeMaxDynamicSharedMemorySize, GEMM_SMEM);
    cudaFuncSetAttribute(flash_mma_kernel,
                         cudaFuncAttributeMaxDynamicSharedMemorySize, FA_SMEM);

    // prologue: pre-round X; transpose+round all 4 weights in one launch
    round_kernel<<<(MROWS * D_MODEL / 4 + 255) / 256, 256>>>(X, Xr, MROWS * D_MODEL / 4);
    dim3 tr_grid(32, 32, 4), tr_blk(32, 8);
    transpose4_kernel<<<tr_grid, tr_blk>>>(Wq, Wk, Wv, Wo, WT, WoT);

    // fused QKV projection: 4096 x 3072
    dim3 qkv_grid(24, MROWS / 128);
    gemm_mma_kernel<1><<<qkv_grid, 256, GEMM_SMEM>>>(Xr, WT, Qp, Kp, Vp);

    dim3 fa_grid(S_LEN / 64, NH, BATCH);
    flash_mma_kernel<<<fa_grid, 128, FA_SMEM>>>(Qp, Kp, Vp, Cp);

    dim3 o_grid(D_MODEL / 128, MROWS / 128);
    gemm_mma_kernel<0><<<o_grid, 256, GEMM_SMEM>>>(Cp, WoT, out, nullptr, nullptr);
}

// round 7
// speedup vs baseline: 7.1654x; 1.7443x over previous
#include <cuda_runtime.h>
#include <cuda_fp16.h>
#include <cstdint>

// Problem constants
#define BATCH   2
#define S_LEN   2048
#define D_MODEL 1024
#define NH      16
#define HD      64
#define MROWS   (BATCH * S_LEN)   // 4096

// Scratch (allocation-free rule: __device__ globals)
__device__ __half g_Xh [MROWS * D_MODEL];
__device__ __half g_Qh [MROWS * D_MODEL];
__device__ __half g_Kh [MROWS * D_MODEL];
__device__ __half g_Vt [D_MODEL * MROWS];      // transposed V: [h*64+d][token]
__device__ __half g_Ch [MROWS * D_MODEL];      // attention output (half)
__device__ __half g_WTh[3 * D_MODEL * D_MODEL];// WqT | WkT | WvT (K-major, half)
__device__ __half g_WoTh[D_MODEL * D_MODEL];

// ---------------------------------------------------------------------------
// Helpers
// ---------------------------------------------------------------------------
__device__ __forceinline__ uint32_t smem_u32(const void* p) {
    uint32_t a;
    asm("{ .reg .u64 t; cvta.to.shared.u64 t, %1; cvt.u32.u64 %0, t; }"
        : "=r"(a) : "l"(p));
    return a;
}

#define CP_ASYNC16(dst, src) \
    asm volatile("cp.async.cg.shared.global [%0], [%1], 16;" :: "r"(dst), "l"(src))
#define CP_COMMIT() asm volatile("cp.async.commit_group;" ::: "memory")
#define CP_WAIT0()  asm volatile("cp.async.wait_group 0;" ::: "memory")
#define CP_WAIT1()  asm volatile("cp.async.wait_group 1;" ::: "memory")

// mma.sync m16n8k16 fp16, fp32 accumulate
#define MMA_F16(d, a, b) \
    asm volatile( \
        "mma.sync.aligned.m16n8k16.row.col.f32.f16.f16.f32 " \
        "{%0,%1,%2,%3}, {%4,%5,%6,%7}, {%8,%9}, {%0,%1,%2,%3};" \
        : "+f"((d)[0]), "+f"((d)[1]), "+f"((d)[2]), "+f"((d)[3]) \
        : "r"((a)[0]), "r"((a)[1]), "r"((a)[2]), "r"((a)[3]), \
          "r"((b)[0]), "r"((b)[1]))

// ---------------------------------------------------------------------------
// fp16 tensor-core GEMM.
// CTA 128x128, 8 warps (4x2), warp tile 32x64, BK=32 (2 x k16), cp.async
// double buffer. MODE 1 = QKV: n-blocks 0-7 -> Qh, 8-15 -> Kh, 16-23 -> Vt
// (transposed store). MODE 0: fp32 output (O projection).
// ---------------------------------------------------------------------------
#define GK    D_MODEL
#define BK    32
#define NST   (GK / BK)          // 32 stages
#define PADH  40                 // halfs per smem row (32 + 8 pad), 80 B
#define TILEH (128 * PADH)       // halfs per tile
#define GEMM_SMEM (2 * 2 * TILEH * 2)   // 40960 bytes

template <int MODE>
__global__ __launch_bounds__(256) void gemm_h_kernel(
    const __half* __restrict__ A, const __half* __restrict__ Bt,
    __half* __restrict__ HQ, __half* __restrict__ HK, __half* __restrict__ HVt,
    float* __restrict__ F0)
{
    extern __shared__ __half smh[];
    const int tid  = threadIdx.x;
    const int lane = tid & 31;
    const int wid  = tid >> 5;
    const int wm   = wid & 3;
    const int wn   = wid >> 2;
    const int g    = lane >> 2;
    const int tg   = lane & 3;
    const int m0   = blockIdx.y * 128;

    int n0, which = 0;
    const __half* Bbase = Bt;
    if (MODE == 1) {
        which = blockIdx.x >> 3;
        Bbase = Bt + (size_t)which * D_MODEL * D_MODEL;
        n0 = (blockIdx.x & 7) * 128;
    } else {
        n0 = blockIdx.x * 128;
    }

    const __half* Ab = A     + (size_t)m0 * GK;
    const __half* Bb = Bbase + (size_t)n0 * GK;

    float acc[2][8][4];
#pragma unroll
    for (int mi = 0; mi < 2; mi++)
#pragma unroll
        for (int ni = 0; ni < 8; ni++)
#pragma unroll
            for (int r = 0; r < 4; r++) acc[mi][ni][r] = 0.f;

    auto load_stage = [&](int s) {
        __half* dA = smh + (s & 1) * 2 * TILEH;
        __half* dB = dA + TILEH;
        const __half* Ak = Ab + s * BK;
        const __half* Bk = Bb + s * BK;
        // 128 rows x 32 halfs (64 B) = 4 x 16B chunks per row, per tile
#pragma unroll
        for (int i = 0; i < 2; i++) {
            const int c   = tid + i * 256;       // 0..511
            const int row = c >> 2;
            const int ch  = c & 3;
            CP_ASYNC16(smem_u32(dA + row * PADH + ch * 8), Ak + (size_t)row * GK + ch * 8);
        }
#pragma unroll
        for (int i = 0; i < 2; i++) {
            const int c   = tid + i * 256;
            const int row = c >> 2;
            const int ch  = c & 3;
            CP_ASYNC16(smem_u32(dB + row * PADH + ch * 8), Bk + (size_t)row * GK + ch * 8);
        }
    };

    load_stage(0);
    CP_COMMIT();

    for (int s = 0; s < NST; s++) {
        if (s + 1 < NST) { load_stage(s + 1); CP_COMMIT(); CP_WAIT1(); }
        else             { CP_WAIT0(); }
        __syncthreads();

        const __half* sA = smh + (s & 1) * 2 * TILEH;
        const __half* sB = sA + TILEH;

#pragma unroll
        for (int kk = 0; kk < 2; kk++) {
            const int k0 = kk * 16;
            uint32_t a[2][4], b[8][2];
#pragma unroll
            for (int mi = 0; mi < 2; mi++) {
                const int r = wm * 32 + mi * 16;
                a[mi][0] = *(const uint32_t*)&sA[(r + g)     * PADH + k0 + 2 * tg];
                a[mi][1] = *(const uint32_t*)&sA[(r + g + 8) * PADH + k0 + 2 * tg];
                a[mi][2] = *(const uint32_t*)&sA[(r + g)     * PADH + k0 + 2 * tg + 8];
                a[mi][3] = *(const uint32_t*)&sA[(r + g + 8) * PADH + k0 + 2 * tg + 8];
            }
#pragma unroll
            for (int ni = 0; ni < 8; ni++) {
                const int cb = wn * 64 + ni * 8;
                b[ni][0] = *(const uint32_t*)&sB[(cb + g) * PADH + k0 + 2 * tg];
                b[ni][1] = *(const uint32_t*)&sB[(cb + g) * PADH + k0 + 2 * tg + 8];
            }
#pragma unroll
            for (int mi = 0; mi < 2; mi++)
#pragma unroll
                for (int ni = 0; ni < 8; ni++)
                    MMA_F16(acc[mi][ni], a[mi], b[ni]);
        }
        __syncthreads();
    }

    // epilogue
#pragma unroll
    for (int mi = 0; mi < 2; mi++) {
#pragma unroll
        for (int ni = 0; ni < 8; ni++) {
            const int r = m0 + wm * 32 + mi * 16 + g;
            const int c = n0 + wn * 64 + ni * 8 + tg * 2;
            const float v0 = acc[mi][ni][0], v1 = acc[mi][ni][1];
            const float v2 = acc[mi][ni][2], v3 = acc[mi][ni][3];
            if (MODE == 0) {
                *(float2*)&F0[(size_t)r * D_MODEL + c]       = make_float2(v0, v1);
                *(float2*)&F0[(size_t)(r + 8) * D_MODEL + c] = make_float2(v2, v3);
            } else if (which < 2) {
                __half* C = (which == 0) ? HQ : HK;
                *(__half2*)&C[(size_t)r * D_MODEL + c]       = __floats2half2_rn(v0, v1);
                *(__half2*)&C[(size_t)(r + 8) * D_MODEL + c] = __floats2half2_rn(v2, v3);
            } else {
                // V: store transposed  Vt[d][token]
                HVt[(size_t)c       * MROWS + r]     = __float2half_rn(v0);
                HVt[(size_t)(c + 1) * MROWS + r]     = __float2half_rn(v1);
                HVt[(size_t)c       * MROWS + r + 8] = __float2half_rn(v2);
                HVt[(size_t)(c + 1) * MROWS + r + 8] = __float2half_rn(v3);
            }
        }
    }
}

// ---------------------------------------------------------------------------
// Batched 1024x1024 transpose, fp32 -> half; z<3 -> WTh slice z; z==3 -> WoTh.
// ---------------------------------------------------------------------------
__global__ __launch_bounds__(256) void transpose4h_kernel(
    const float* __restrict__ w0, const float* __restrict__ w1,
    const float* __restrict__ w2, const float* __restrict__ w3,
    __half* __restrict__ wt, __half* __restrict__ wot)
{
    __shared__ float t[32][33];
    const int z = blockIdx.z;
    const float* in = (z == 0) ? w0 : (z == 1) ? w1 : (z == 2) ? w2 : w3;
    __half* out = (z < 3) ? (wt + (size_t)z * D_MODEL * D_MODEL) : wot;

    int x  = blockIdx.x * 32 + threadIdx.x;
    int y0 = blockIdx.y * 32 + threadIdx.y;
#pragma unroll
    for (int j = 0; j < 32; j += 8)
        t[threadIdx.y + j][threadIdx.x] = in[(size_t)(y0 + j) * D_MODEL + x];
    __syncthreads();
    x  = blockIdx.y * 32 + threadIdx.x;
    y0 = blockIdx.x * 32 + threadIdx.y;
#pragma unroll
    for (int j = 0; j < 32; j += 8)
        out[(size_t)(y0 + j) * D_MODEL + x] = __float2half_rn(t[threadIdx.x][threadIdx.y + j]);
}

// elementwise fp32 -> half
__global__ __launch_bounds__(256) void convh_kernel(
    const float* __restrict__ in, __half* __restrict__ out, int n4)
{
    int i = blockIdx.x * blockDim.x + threadIdx.x;
    if (i < n4) {
        float4 v = ((const float4*)in)[i];
        __half2 h0 = __floats2half2_rn(v.x, v.y);
        __half2 h1 = __floats2half2_rn(v.z, v.w);
        ((uint2*)out)[i] = make_uint2(*(uint32_t*)&h0, *(uint32_t*)&h1);
    }
}

// ---------------------------------------------------------------------------
// fp16 tensor-core causal flash attention, cp.async double-buffered K/Vt.
// Block = 64 q rows of one (b,h); 128 threads = 4 warps x 16 q rows.
// K row-major [key][d]; V pre-transposed globally -> Vt tiles [d][key].
// ---------------------------------------------------------------------------
#define FPH 72
// Qs[64] + Ks[2][64] + Vts[2][64] + Pb[4][16] rows of FPH halfs
#define FA_SMEM ((64 + 128 + 128 + 64) * FPH * 2)   // 55296 bytes

__global__ __launch_bounds__(128) void flash_h_kernel(
    const __half* __restrict__ Qh, const __half* __restrict__ Kh,
    const __half* __restrict__ Vt, __half* __restrict__ Ch)
{
    extern __shared__ __half fsh[];
    __half* Qs  = fsh;                      // [64][FPH]
    __half* Ksb = Qs + 64 * FPH;            // 2 x [64][FPH]
    __half* Vsb = Ksb + 2 * 64 * FPH;       // 2 x [64][FPH]  (Vt tiles)
    __half* Pb  = Vsb + 2 * 64 * FPH;       // 4 x [16][FPH]

    const int tid  = threadIdx.x;
    const int lane = tid & 31;
    const int wid  = tid >> 5;
    const int g    = lane >> 2;
    const int tg   = lane & 3;
    const int b    = blockIdx.z;
    const int h    = blockIdx.y;
    const int q0   = (gridDim.x - 1 - blockIdx.x) * 64;   // heavy tiles first

    const __half* Kb  = Kh + (size_t)b * S_LEN * D_MODEL + (size_t)h * HD;
    const __half* Vtb = Vt + (size_t)h * HD * MROWS + (size_t)b * S_LEN;

    auto prefetch = [&](int k0, int buf) {
        __half* dK = Ksb + buf * 64 * FPH;
        __half* dV = Vsb + buf * 64 * FPH;
#pragma unroll
        for (int i = 0; i < 4; i++) {
            const int c   = tid + i * 128;     // 0..511
            const int row = c >> 3;            // 0..63 (key)
            const int ch  = c & 7;             // 16B chunk (8 halfs)
            CP_ASYNC16(smem_u32(dK + row * FPH + ch * 8),
                       Kb + (size_t)(k0 + row) * D_MODEL + ch * 8);
        }
#pragma unroll
        for (int i = 0; i < 4; i++) {
            const int c   = tid + i * 128;
            const int row = c >> 3;            // 0..63 (d)
            const int ch  = c & 7;
            CP_ASYNC16(smem_u32(dV + row * FPH + ch * 8),
                       Vtb + (size_t)row * MROWS + k0 + ch * 8);
        }
    };

    // load Q tile: thread covers half a row (32 halfs = 64 B)
    {
        const int lrow = tid >> 1;
        const int lcol = (tid & 1) * 32;
        const __half* qp = Qh + ((size_t)(b * S_LEN + q0 + lrow)) * D_MODEL
                              + (size_t)h * HD + lcol;
#pragma unroll
        for (int c = 0; c < 32; c += 8)
            *(float4*)&Qs[lrow * FPH + lcol + c] = *(const float4*)(qp + c);
    }

    float o[8][4];
#pragma unroll
    for (int d = 0; d < 8; d++)
#pragma unroll
        for (int r = 0; r < 4; r++) o[d][r] = 0.f;
    float mrun[2] = {-1e30f, -1e30f};
    float lrun[2] = {0.f, 0.f};

    __half* Pw = Pb + wid * 16 * FPH;
    const int qrow_lo = q0 + wid * 16 + g;
    const int ntiles  = q0 / 64 + 1;

    prefetch(0, 0);
    CP_COMMIT();

    for (int t = 0; t < ntiles; t++) {
        const int k0  = t * 64;
        const int buf = t & 1;
        if (t + 1 < ntiles) { prefetch((t + 1) * 64, buf ^ 1); CP_COMMIT(); CP_WAIT1(); }
        else                { CP_WAIT0(); }
        __syncthreads();

        const __half* Ks = Ksb + buf * 64 * FPH;
        const __half* Vs = Vsb + buf * 64 * FPH;

        // ---- S = Q * K^T  (4 x k16) ----
        float sf[8][4];
#pragma unroll
        for (int nb = 0; nb < 8; nb++)
#pragma unroll
            for (int r = 0; r < 4; r++) sf[nb][r] = 0.f;

#pragma unroll
        for (int kk = 0; kk < 4; kk++) {
            const int kd = kk * 16;
            const int ar = wid * 16 + g;
            uint32_t a[4];
            a[0] = *(const uint32_t*)&Qs[(ar)     * FPH + kd + 2 * tg];
            a[1] = *(const uint32_t*)&Qs[(ar + 8) * FPH + kd + 2 * tg];
            a[2] = *(const uint32_t*)&Qs[(ar)     * FPH + kd + 2 * tg + 8];
            a[3] = *(const uint32_t*)&Qs[(ar + 8) * FPH + kd + 2 * tg + 8];
#pragma unroll
            for (int nb = 0; nb < 8; nb++) {
                uint32_t bfr[2];
                bfr[0] = *(const uint32_t*)&Ks[(nb * 8 + g) * FPH + kd + 2 * tg];
                bfr[1] = *(const uint32_t*)&Ks[(nb * 8 + g) * FPH + kd + 2 * tg + 8];
                MMA_F16(sf[nb], a, bfr);
            }
        }

        // ---- scale + causal mask (diagonal tile only) ----
        const bool diag = (k0 == q0);
#pragma unroll
        for (int nb = 0; nb < 8; nb++) {
#pragma unroll
            for (int r = 0; r < 4; r++) {
                float s = sf[nb][r] * 0.125f;
                if (diag) {
                    const int kcol = k0 + nb * 8 + tg * 2 + (r & 1);
                    const int qrow = qrow_lo + (r >> 1) * 8;
                    if (kcol > qrow) s = -1e30f;
                }
                sf[nb][r] = s;
            }
        }

        // ---- online softmax (rows g and g+8) ----
#pragma unroll
        for (int r = 0; r < 2; r++) {
            float mt = -1e30f;
#pragma unroll
            for (int nb = 0; nb < 8; nb++)
                mt = fmaxf(mt, fmaxf(sf[nb][r * 2], sf[nb][r * 2 + 1]));
            mt = fmaxf(mt, __shfl_xor_sync(0xFFFFFFFFu, mt, 1));
            mt = fmaxf(mt, __shfl_xor_sync(0xFFFFFFFFu, mt, 2));
            const float mnew  = fmaxf(mrun[r], mt);
            const float alpha = __expf(mrun[r] - mnew);
            float ls = 0.f;
#pragma unroll
            for (int nb = 0; nb < 8; nb++) {
                float p0 = __expf(sf[nb][r * 2]     - mnew);
                float p1 = __expf(sf[nb][r * 2 + 1] - mnew);
                ls += p0 + p1;
                sf[nb][r * 2]     = p0;
                sf[nb][r * 2 + 1] = p1;
            }
            ls += __shfl_xor_sync(0xFFFFFFFFu, ls, 1);
            ls += __shfl_xor_sync(0xFFFFFFFFu, ls, 2);
            lrun[r] = lrun[r] * alpha + ls;
            mrun[r] = mnew;
#pragma unroll
            for (int d = 0; d < 8; d++) {
                o[d][r * 2]     *= alpha;
                o[d][r * 2 + 1] *= alpha;
            }
        }

        // ---- stage P (half) into warp-private smem ----
#pragma unroll
        for (int nb = 0; nb < 8; nb++) {
            *(__half2*)&Pw[g * FPH + nb * 8 + tg * 2] =
                __floats2half2_rn(sf[nb][0], sf[nb][1]);
            *(__half2*)&Pw[(g + 8) * FPH + nb * 8 + tg * 2] =
                __floats2half2_rn(sf[nb][2], sf[nb][3]);
        }
        __syncwarp();

        // ---- O += P * V  (B-fragments from Vt tile: half2 in key dim) ----
#pragma unroll
        for (int kk = 0; kk < 4; kk++) {
            const int kd = kk * 16;
            uint32_t a[4];
            a[0] = *(const uint32_t*)&Pw[(g)     * FPH + kd + 2 * tg];
            a[1] = *(const uint32_t*)&Pw[(g + 8) * FPH + kd + 2 * tg];
            a[2] = *(const uint32_t*)&Pw[(g)     * FPH + kd + 2 * tg + 8];
            a[3] = *(const uint32_t*)&Pw[(g + 8) * FPH + kd + 2 * tg + 8];
#pragma unroll
            for (int db = 0; db < 8; db++) {
                uint32_t bfr[2];
                bfr[0] = *(const uint32_t*)&Vs[(db * 8 + g) * FPH + kd + 2 * tg];
                bfr[1] = *(const uint32_t*)&Vs[(db * 8 + g) * FPH + kd + 2 * tg + 8];
                MMA_F16(o[db], a, bfr);
            }
        }
        __syncthreads();   // all warps done with buf before overwrite
    }

    // ---- epilogue: normalize, convert to half, store ----
    const float inv0 = 1.f / lrun[0];
    const float inv1 = 1.f / lrun[1];
    __half* c0 = Ch + ((size_t)(b * S_LEN + qrow_lo)) * D_MODEL + (size_t)h * HD;
    __half* c1 = c0 + 8 * D_MODEL;
#pragma unroll
    for (int db = 0; db < 8; db++) {
        const int c = db * 8 + tg * 2;
        *(__half2*)(c0 + c) = __floats2half2_rn(o[db][0] * inv0, o[db][1] * inv0);
        *(__half2*)(c1 + c) = __floats2half2_rn(o[db][2] * inv1, o[db][3] * inv1);
    }
}

// ---------------------------------------------------------------------------
extern "C" void kernel_launch(void* const* d_in, const int* in_sizes, int n_in,
                              void* d_out, int out_size)
{
    const float* X  = (const float*)d_in[0];
    const float* Wq = (const float*)d_in[1];
    const float* Wk = (const float*)d_in[2];
    const float* Wv = (const float*)d_in[3];
    const float* Wo = (const float*)d_in[4];
    float* out = (float*)d_out;

    __half *Xh, *Qh, *Kh, *Vt, *Ch, *WTh, *WoTh;
    cudaGetSymbolAddress((void**)&Xh,   g_Xh);
    cudaGetSymbolAddress((void**)&Qh,   g_Qh);
    cudaGetSymbolAddress((void**)&Kh,   g_Kh);
    cudaGetSymbolAddress((void**)&Vt,   g_Vt);
    cudaGetSymbolAddress((void**)&Ch,   g_Ch);
    cudaGetSymbolAddress((void**)&WTh,  g_WTh);
    cudaGetSymbolAddress((void**)&WoTh, g_WoTh);

    cudaFuncSetAttribute(gemm_h_kernel<0>,
                         cudaFuncAttributeMaxDynamicSharedMemorySize, GEMM_SMEM);
    cudaFuncSetAttribute(gemm_h_kernel<1>,
                         cudaFuncAttributeMaxDynamicSharedMemorySize, GEMM_SMEM);
    cudaFuncSetAttribute(flash_h_kernel,
                         cudaFuncAttributeMaxDynamicSharedMemorySize, FA_SMEM);

    // prologue: X -> half; transpose+convert all 4 weights
    convh_kernel<<<(MROWS * D_MODEL / 4 + 255) / 256, 256>>>(X, Xh, MROWS * D_MODEL / 4);
    dim3 tr_grid(32, 32, 4), tr_blk(32, 8);
    transpose4h_kernel<<<tr_grid, tr_blk>>>(Wq, Wk, Wv, Wo, WTh, WoTh);

    // fused QKV projection: 4096 x 3072 (V written transposed)
    dim3 qkv_grid(24, MROWS / 128);
    gemm_h_kernel<1><<<qkv_grid, 256, GEMM_SMEM>>>(Xh, WTh, Qh, Kh, Vt, nullptr);

    dim3 fa_grid(S_LEN / 64, NH, BATCH);
    flash_h_kernel<<<fa_grid, 128, FA_SMEM>>>(Qh, Kh, Vt, Ch);

    // output projection -> fp32
    dim3 o_grid(D_MODEL / 128, MROWS / 128);
    gemm_h_kernel<0><<<o_grid, 256, GEMM_SMEM>>>(Ch, WoTh, nullptr, nullptr, nullptr, out);
}

// round 10
// speedup vs baseline: 7.4796x; 1.0438x over previous
#include <cuda_runtime.h>
#include <cuda_fp16.h>
#include <cstdint>

// Problem constants
#define BATCH   2
#define S_LEN   2048
#define D_MODEL 1024
#define NH      16
#define HD      64
#define MROWS   (BATCH * S_LEN)   // 4096

// Scratch (allocation-free rule: __device__ globals)
__device__ __half g_Xh [MROWS * D_MODEL];
__device__ __half g_Qh [MROWS * D_MODEL];
__device__ __half g_Kh [MROWS * D_MODEL];
__device__ __half g_Vt [D_MODEL * MROWS];      // transposed V: [h*64+d][token]
__device__ __half g_Ch [MROWS * D_MODEL];      // attention output (half)
__device__ __half g_WTh[3 * D_MODEL * D_MODEL];// WqT | WkT | WvT (K-major, half)
__device__ __half g_WoTh[D_MODEL * D_MODEL];

// ---------------------------------------------------------------------------
// Helpers
// ---------------------------------------------------------------------------
__device__ __forceinline__ uint32_t smem_u32(const void* p) {
    uint32_t a;
    asm("{ .reg .u64 t; cvta.to.shared.u64 t, %1; cvt.u32.u64 %0, t; }"
        : "=r"(a) : "l"(p));
    return a;
}

#define CP_ASYNC16(dst, src) \
    asm volatile("cp.async.cg.shared.global [%0], [%1], 16;" :: "r"(dst), "l"(src))
#define CP_COMMIT() asm volatile("cp.async.commit_group;" ::: "memory")
#define CP_WAIT0()  asm volatile("cp.async.wait_group 0;" ::: "memory")
#define CP_WAIT1()  asm volatile("cp.async.wait_group 1;" ::: "memory")

// mma.sync m16n8k16 fp16, fp32 accumulate
#define MMA_F16(d, a, b) \
    asm volatile( \
        "mma.sync.aligned.m16n8k16.row.col.f32.f16.f16.f32 " \
        "{%0,%1,%2,%3}, {%4,%5,%6,%7}, {%8,%9}, {%0,%1,%2,%3};" \
        : "+f"((d)[0]), "+f"((d)[1]), "+f"((d)[2]), "+f"((d)[3]) \
        : "r"((a)[0]), "r"((a)[1]), "r"((a)[2]), "r"((a)[3]), \
          "r"((b)[0]), "r"((b)[1]))

// ---------------------------------------------------------------------------
// fp16 tensor-core GEMM (proven in R7).
// CTA 128x128, 8 warps (4x2), warp tile 32x64, BK=32, cp.async double buffer.
// MODE 1 = QKV fused (V stored transposed); MODE 0 = fp32 output.
// ---------------------------------------------------------------------------
#define GK    D_MODEL
#define BK    32
#define NST   (GK / BK)
#define PADH  40
#define TILEH (128 * PADH)
#define GEMM_SMEM (2 * 2 * TILEH * 2)   // 40960 bytes

template <int MODE>
__global__ __launch_bounds__(256) void gemm_h_kernel(
    const __half* __restrict__ A, const __half* __restrict__ Bt,
    __half* __restrict__ HQ, __half* __restrict__ HK, __half* __restrict__ HVt,
    float* __restrict__ F0)
{
    extern __shared__ __half smh[];
    const int tid  = threadIdx.x;
    const int lane = tid & 31;
    const int wid  = tid >> 5;
    const int wm   = wid & 3;
    const int wn   = wid >> 2;
    const int g    = lane >> 2;
    const int tg   = lane & 3;
    const int m0   = blockIdx.y * 128;

    int n0, which = 0;
    const __half* Bbase = Bt;
    if (MODE == 1) {
        which = blockIdx.x >> 3;
        Bbase = Bt + (size_t)which * D_MODEL * D_MODEL;
        n0 = (blockIdx.x & 7) * 128;
    } else {
        n0 = blockIdx.x * 128;
    }

    const __half* Ab = A     + (size_t)m0 * GK;
    const __half* Bb = Bbase + (size_t)n0 * GK;

    float acc[2][8][4];
#pragma unroll
    for (int mi = 0; mi < 2; mi++)
#pragma unroll
        for (int ni = 0; ni < 8; ni++)
#pragma unroll
            for (int r = 0; r < 4; r++) acc[mi][ni][r] = 0.f;

    auto load_stage = [&](int s) {
        __half* dA = smh + (s & 1) * 2 * TILEH;
        __half* dB = dA + TILEH;
        const __half* Ak = Ab + s * BK;
        const __half* Bk = Bb + s * BK;
#pragma unroll
        for (int i = 0; i < 2; i++) {
            const int c   = tid + i * 256;
            const int row = c >> 2;
            const int ch  = c & 3;
            CP_ASYNC16(smem_u32(dA + row * PADH + ch * 8), Ak + (size_t)row * GK + ch * 8);
        }
#pragma unroll
        for (int i = 0; i < 2; i++) {
            const int c   = tid + i * 256;
            const int row = c >> 2;
            const int ch  = c & 3;
            CP_ASYNC16(smem_u32(dB + row * PADH + ch * 8), Bk + (size_t)row * GK + ch * 8);
        }
    };

    load_stage(0);
    CP_COMMIT();

    for (int s = 0; s < NST; s++) {
        if (s + 1 < NST) { load_stage(s + 1); CP_COMMIT(); CP_WAIT1(); }
        else             { CP_WAIT0(); }
        __syncthreads();

        const __half* sA = smh + (s & 1) * 2 * TILEH;
        const __half* sB = sA + TILEH;

#pragma unroll
        for (int kk = 0; kk < 2; kk++) {
            const int k0 = kk * 16;
            uint32_t a[2][4], b[8][2];
#pragma unroll
            for (int mi = 0; mi < 2; mi++) {
                const int r = wm * 32 + mi * 16;
                a[mi][0] = *(const uint32_t*)&sA[(r + g)     * PADH + k0 + 2 * tg];
                a[mi][1] = *(const uint32_t*)&sA[(r + g + 8) * PADH + k0 + 2 * tg];
                a[mi][2] = *(const uint32_t*)&sA[(r + g)     * PADH + k0 + 2 * tg + 8];
                a[mi][3] = *(const uint32_t*)&sA[(r + g + 8) * PADH + k0 + 2 * tg + 8];
            }
#pragma unroll
            for (int ni = 0; ni < 8; ni++) {
                const int cb = wn * 64 + ni * 8;
                b[ni][0] = *(const uint32_t*)&sB[(cb + g) * PADH + k0 + 2 * tg];
                b[ni][1] = *(const uint32_t*)&sB[(cb + g) * PADH + k0 + 2 * tg + 8];
            }
#pragma unroll
            for (int mi = 0; mi < 2; mi++)
#pragma unroll
                for (int ni = 0; ni < 8; ni++)
                    MMA_F16(acc[mi][ni], a[mi], b[ni]);
        }
        __syncthreads();
    }

#pragma unroll
    for (int mi = 0; mi < 2; mi++) {
#pragma unroll
        for (int ni = 0; ni < 8; ni++) {
            const int r = m0 + wm * 32 + mi * 16 + g;
            const int c = n0 + wn * 64 + ni * 8 + tg * 2;
            const float v0 = acc[mi][ni][0], v1 = acc[mi][ni][1];
            const float v2 = acc[mi][ni][2], v3 = acc[mi][ni][3];
            if (MODE == 0) {
                *(float2*)&F0[(size_t)r * D_MODEL + c]       = make_float2(v0, v1);
                *(float2*)&F0[(size_t)(r + 8) * D_MODEL + c] = make_float2(v2, v3);
            } else if (which < 2) {
                __half* C = (which == 0) ? HQ : HK;
                *(__half2*)&C[(size_t)r * D_MODEL + c]       = __floats2half2_rn(v0, v1);
                *(__half2*)&C[(size_t)(r + 8) * D_MODEL + c] = __floats2half2_rn(v2, v3);
            } else {
                HVt[(size_t)c       * MROWS + r]     = __float2half_rn(v0);
                HVt[(size_t)(c + 1) * MROWS + r]     = __float2half_rn(v1);
                HVt[(size_t)c       * MROWS + r + 8] = __float2half_rn(v2);
                HVt[(size_t)(c + 1) * MROWS + r + 8] = __float2half_rn(v3);
            }
        }
    }
}

// ---------------------------------------------------------------------------
// Batched 1024x1024 transpose, fp32 -> half.
// ---------------------------------------------------------------------------
__global__ __launch_bounds__(256) void transpose4h_kernel(
    const float* __restrict__ w0, const float* __restrict__ w1,
    const float* __restrict__ w2, const float* __restrict__ w3,
    __half* __restrict__ wt, __half* __restrict__ wot)
{
    __shared__ float t[32][33];
    const int z = blockIdx.z;
    const float* in = (z == 0) ? w0 : (z == 1) ? w1 : (z == 2) ? w2 : w3;
    __half* out = (z < 3) ? (wt + (size_t)z * D_MODEL * D_MODEL) : wot;

    int x  = blockIdx.x * 32 + threadIdx.x;
    int y0 = blockIdx.y * 32 + threadIdx.y;
#pragma unroll
    for (int j = 0; j < 32; j += 8)
        t[threadIdx.y + j][threadIdx.x] = in[(size_t)(y0 + j) * D_MODEL + x];
    __syncthreads();
    x  = blockIdx.y * 32 + threadIdx.x;
    y0 = blockIdx.x * 32 + threadIdx.y;
#pragma unroll
    for (int j = 0; j < 32; j += 8)
        out[(size_t)(y0 + j) * D_MODEL + x] = __float2half_rn(t[threadIdx.x][threadIdx.y + j]);
}

__global__ __launch_bounds__(256) void convh_kernel(
    const float* __restrict__ in, __half* __restrict__ out, int n4)
{
    int i = blockIdx.x * blockDim.x + threadIdx.x;
    if (i < n4) {
        float4 v = ((const float4*)in)[i];
        __half2 h0 = __floats2half2_rn(v.x, v.y);
        __half2 h1 = __floats2half2_rn(v.z, v.w);
        ((uint2*)out)[i] = make_uint2(*(uint32_t*)&h0, *(uint32_t*)&h1);
    }
}

// ---------------------------------------------------------------------------
// fp16 flash attention v2: Q fragments register-resident, P stays in
// registers (S C-fragment layout == PV A-fragment layout), exp2 softmax,
// no P smem. Block = 64 q rows; 128 threads = 4 warps x 16 q rows.
// ---------------------------------------------------------------------------
#define FPH 72
// Qs[64] + Ks[2][64] + Vts[2][64] rows of FPH halfs
#define FA_SMEM ((64 + 128 + 128) * FPH * 2)   // 46080 bytes

__global__ __launch_bounds__(128) void flash_h_kernel(
    const __half* __restrict__ Qh, const __half* __restrict__ Kh,
    const __half* __restrict__ Vt, __half* __restrict__ Ch)
{
    extern __shared__ __half fsh[];
    __half* Qs  = fsh;                      // [64][FPH]
    __half* Ksb = Qs + 64 * FPH;            // 2 x [64][FPH]
    __half* Vsb = Ksb + 2 * 64 * FPH;       // 2 x [64][FPH]

    const int tid  = threadIdx.x;
    const int lane = tid & 31;
    const int wid  = tid >> 5;
    const int g    = lane >> 2;
    const int tg   = lane & 3;
    const int b    = blockIdx.z;
    const int h    = blockIdx.y;
    const int q0   = (gridDim.x - 1 - blockIdx.x) * 64;   // heavy tiles first

    const __half* Kb  = Kh + (size_t)b * S_LEN * D_MODEL + (size_t)h * HD;
    const __half* Vtb = Vt + (size_t)h * HD * MROWS + (size_t)b * S_LEN;

    auto prefetch = [&](int k0, int buf) {
        __half* dK = Ksb + buf * 64 * FPH;
        __half* dV = Vsb + buf * 64 * FPH;
#pragma unroll
        for (int i = 0; i < 4; i++) {
            const int c   = tid + i * 128;
            const int row = c >> 3;
            const int ch  = c & 7;
            CP_ASYNC16(smem_u32(dK + row * FPH + ch * 8),
                       Kb + (size_t)(k0 + row) * D_MODEL + ch * 8);
        }
#pragma unroll
        for (int i = 0; i < 4; i++) {
            const int c   = tid + i * 128;
            const int row = c >> 3;
            const int ch  = c & 7;
            CP_ASYNC16(smem_u32(dV + row * FPH + ch * 8),
                       Vtb + (size_t)row * MROWS + k0 + ch * 8);
        }
    };

    // stage Q tile into smem (coalesced), then lift fragments to registers
    {
        const int lrow = tid >> 1;
        const int lcol = (tid & 1) * 32;
        const __half* qp = Qh + ((size_t)(b * S_LEN + q0 + lrow)) * D_MODEL
                              + (size_t)h * HD + lcol;
#pragma unroll
        for (int c = 0; c < 32; c += 8)
            *(float4*)&Qs[lrow * FPH + lcol + c] = *(const float4*)(qp + c);
    }
    prefetch(0, 0);
    CP_COMMIT();
    __syncthreads();

    uint32_t qf[4][4];          // Q fragments, all 4 k16 blocks
    {
        const int ar = wid * 16 + g;
#pragma unroll
        for (int kk = 0; kk < 4; kk++) {
            const int kd = kk * 16;
            qf[kk][0] = *(const uint32_t*)&Qs[(ar)     * FPH + kd + 2 * tg];
            qf[kk][1] = *(const uint32_t*)&Qs[(ar + 8) * FPH + kd + 2 * tg];
            qf[kk][2] = *(const uint32_t*)&Qs[(ar)     * FPH + kd + 2 * tg + 8];
            qf[kk][3] = *(const uint32_t*)&Qs[(ar + 8) * FPH + kd + 2 * tg + 8];
        }
    }

    float o[8][4];
#pragma unroll
    for (int d = 0; d < 8; d++)
#pragma unroll
        for (int r = 0; r < 4; r++) o[d][r] = 0.f;
    float mrun[2] = {-1e30f, -1e30f};
    float lrun[2] = {0.f, 0.f};

    const int qrow_lo = q0 + wid * 16 + g;
    const int ntiles  = q0 / 64 + 1;
    const float sc = 0.125f * 1.44269504f;   // (1/sqrt(64)) * log2(e)

    for (int t = 0; t < ntiles; t++) {
        const int k0  = t * 64;
        const int buf = t & 1;
        if (t + 1 < ntiles) { prefetch((t + 1) * 64, buf ^ 1); CP_COMMIT(); CP_WAIT1(); }
        else                { CP_WAIT0(); }
        __syncthreads();

        const __half* Ks = Ksb + buf * 64 * FPH;
        const __half* Vs = Vsb + buf * 64 * FPH;

        // ---- S = Q * K^T  (log2-scaled) ----
        float sf[8][4];
#pragma unroll
        for (int nb = 0; nb < 8; nb++)
#pragma unroll
            for (int r = 0; r < 4; r++) sf[nb][r] = 0.f;

#pragma unroll
        for (int kk = 0; kk < 4; kk++) {
            const int kd = kk * 16;
#pragma unroll
            for (int nb = 0; nb < 8; nb++) {
                uint32_t bfr[2];
                bfr[0] = *(const uint32_t*)&Ks[(nb * 8 + g) * FPH + kd + 2 * tg];
                bfr[1] = *(const uint32_t*)&Ks[(nb * 8 + g) * FPH + kd + 2 * tg + 8];
                MMA_F16(sf[nb], qf[kk], bfr);
            }
        }

        // ---- scale (log2 domain) + causal mask (diagonal tile only) ----
        const bool diag = (k0 == q0);
#pragma unroll
        for (int nb = 0; nb < 8; nb++) {
#pragma unroll
            for (int r = 0; r < 4; r++) {
                float s = sf[nb][r] * sc;
                if (diag) {
                    const int kcol = k0 + nb * 8 + tg * 2 + (r & 1);
                    const int qrow = qrow_lo + (r >> 1) * 8;
                    if (kcol > qrow) s = -1e30f;
                }
                sf[nb][r] = s;
            }
        }

        // ---- online softmax in log2 domain (rows g, g+8) ----
        uint32_t plo[8], phi[8];
#pragma unroll
        for (int r = 0; r < 2; r++) {
            float mt = -1e30f;
#pragma unroll
            for (int nb = 0; nb < 8; nb++)
                mt = fmaxf(mt, fmaxf(sf[nb][r * 2], sf[nb][r * 2 + 1]));
            mt = fmaxf(mt, __shfl_xor_sync(0xFFFFFFFFu, mt, 1));
            mt = fmaxf(mt, __shfl_xor_sync(0xFFFFFFFFu, mt, 2));
            const float mnew  = fmaxf(mrun[r], mt);
            const float alpha = exp2f(mrun[r] - mnew);
            float ls = 0.f;
#pragma unroll
            for (int nb = 0; nb < 8; nb++) {
                const float p0 = exp2f(sf[nb][r * 2]     - mnew);
                const float p1 = exp2f(sf[nb][r * 2 + 1] - mnew);
                ls += p0 + p1;
                const __half2 ph = __floats2half2_rn(p0, p1);
                if (r == 0) plo[nb] = *(const uint32_t*)&ph;
                else        phi[nb] = *(const uint32_t*)&ph;
            }
            ls += __shfl_xor_sync(0xFFFFFFFFu, ls, 1);
            ls += __shfl_xor_sync(0xFFFFFFFFu, ls, 2);
            lrun[r] = lrun[r] * alpha + ls;
            mrun[r] = mnew;
#pragma unroll
            for (int d = 0; d < 8; d++) {
                o[d][r * 2]     *= alpha;
                o[d][r * 2 + 1] *= alpha;
            }
        }

        // ---- O += P * V : P already in A-fragment layout ----
#pragma unroll
        for (int kk = 0; kk < 4; kk++) {
            const int kd = kk * 16;
            uint32_t a[4];
            a[0] = plo[2 * kk];
            a[1] = phi[2 * kk];
            a[2] = plo[2 * kk + 1];
            a[3] = phi[2 * kk + 1];
#pragma unroll
            for (int db = 0; db < 8; db++) {
                uint32_t bfr[2];
                bfr[0] = *(const uint32_t*)&Vs[(db * 8 + g) * FPH + kd + 2 * tg];
                bfr[1] = *(const uint32_t*)&Vs[(db * 8 + g) * FPH + kd + 2 * tg + 8];
                MMA_F16(o[db], a, bfr);
            }
        }
        __syncthreads();   // all warps done with buf before overwrite
    }

    // ---- epilogue: normalize, convert to half, store ----
    const float inv0 = 1.f / lrun[0];
    const float inv1 = 1.f / lrun[1];
    __half* c0 = Ch + ((size_t)(b * S_LEN + qrow_lo)) * D_MODEL + (size_t)h * HD;
    __half* c1 = c0 + 8 * D_MODEL;
#pragma unroll
    for (int db = 0; db < 8; db++) {
        const int c = db * 8 + tg * 2;
        *(__half2*)(c0 + c) = __floats2half2_rn(o[db][0] * inv0, o[db][1] * inv0);
        *(__half2*)(c1 + c) = __floats2half2_rn(o[db][2] * inv1, o[db][3] * inv1);
    }
}

// ---------------------------------------------------------------------------
extern "C" void kernel_launch(void* const* d_in, const int* in_sizes, int n_in,
                              void* d_out, int out_size)
{
    const float* X  = (const float*)d_in[0];
    const float* Wq = (const float*)d_in[1];
    const float* Wk = (const float*)d_in[2];
    const float* Wv = (const float*)d_in[3];
    const float* Wo = (const float*)d_in[4];
    float* out = (float*)d_out;

    __half *Xh, *Qh, *Kh, *Vt, *Ch, *WTh, *WoTh;
    cudaGetSymbolAddress((void**)&Xh,   g_Xh);
    cudaGetSymbolAddress((void**)&Qh,   g_Qh);
    cudaGetSymbolAddress((void**)&Kh,   g_Kh);
    cudaGetSymbolAddress((void**)&Vt,   g_Vt);
    cudaGetSymbolAddress((void**)&Ch,   g_Ch);
    cudaGetSymbolAddress((void**)&WTh,  g_WTh);
    cudaGetSymbolAddress((void**)&WoTh, g_WoTh);

    cudaFuncSetAttribute(gemm_h_kernel<0>,
                         cudaFuncAttributeMaxDynamicSharedMemorySize, GEMM_SMEM);
    cudaFuncSetAttribute(gemm_h_kernel<1>,
                         cudaFuncAttributeMaxDynamicSharedMemorySize, GEMM_SMEM);
    cudaFuncSetAttribute(flash_h_kernel,
                         cudaFuncAttributeMaxDynamicSharedMemorySize, FA_SMEM);

    convh_kernel<<<(MROWS * D_MODEL / 4 + 255) / 256, 256>>>(X, Xh, MROWS * D_MODEL / 4);
    dim3 tr_grid(32, 32, 4), tr_blk(32, 8);
    transpose4h_kernel<<<tr_grid, tr_blk>>>(Wq, Wk, Wv, Wo, WTh, WoTh);

    dim3 qkv_grid(24, MROWS / 128);
    gemm_h_kernel<1><<<qkv_grid, 256, GEMM_SMEM>>>(Xh, WTh, Qh, Kh, Vt, nullptr);

    dim3 fa_grid(S_LEN / 64, NH, BATCH);
    flash_h_kernel<<<fa_grid, 128, FA_SMEM>>>(Qh, Kh, Vt, Ch);

    dim3 o_grid(D_MODEL / 128, MROWS / 128);
    gemm_h_kernel<0><<<o_grid, 256, GEMM_SMEM>>>(Ch, WoTh, nullptr, nullptr, nullptr, out);
}

// round 15
// speedup vs baseline: 7.9975x; 1.0692x over previous
#include <cuda_runtime.h>
#include <cuda_fp16.h>
#include <cstdint>

// Problem constants
#define BATCH   2
#define S_LEN   2048
#define D_MODEL 1024
#define NH      16
#define HD      64
#define MROWS   (BATCH * S_LEN)   // 4096

// Scratch (allocation-free rule: __device__ globals)
__device__ __half g_Xh [MROWS * D_MODEL];
__device__ __half g_Qh [MROWS * D_MODEL];
__device__ __half g_Kh [MROWS * D_MODEL];
__device__ __half g_Vt [D_MODEL * MROWS];      // transposed V: [h*64+d][token]
__device__ __half g_Ch [MROWS * D_MODEL];      // attention output (half)
__device__ __half g_WTh[3 * D_MODEL * D_MODEL];// WqT | WkT | WvT (K-major, half)
__device__ __half g_WoTh[D_MODEL * D_MODEL];

// ---------------------------------------------------------------------------
// Helpers
// ---------------------------------------------------------------------------
__device__ __forceinline__ uint32_t smem_u32(const void* p) {
    uint32_t a;
    asm("{ .reg .u64 t; cvta.to.shared.u64 t, %1; cvt.u32.u64 %0, t; }"
        : "=r"(a) : "l"(p));
    return a;
}

#define CP_ASYNC16(dst, src) \
    asm volatile("cp.async.cg.shared.global [%0], [%1], 16;" :: "r"(dst), "l"(src))
#define CP_COMMIT() asm volatile("cp.async.commit_group;" ::: "memory")
#define CP_WAIT0()  asm volatile("cp.async.wait_group 0;" ::: "memory")
#define CP_WAIT1()  asm volatile("cp.async.wait_group 1;" ::: "memory")

// mma.sync m16n8k16 fp16, fp32 accumulate
#define MMA_F16(d, a, b) \
    asm volatile( \
        "mma.sync.aligned.m16n8k16.row.col.f32.f16.f16.f32 " \
        "{%0,%1,%2,%3}, {%4,%5,%6,%7}, {%8,%9}, {%0,%1,%2,%3};" \
        : "+f"((d)[0]), "+f"((d)[1]), "+f"((d)[2]), "+f"((d)[3]) \
        : "r"((a)[0]), "r"((a)[1]), "r"((a)[2]), "r"((a)[3]), \
          "r"((b)[0]), "r"((b)[1]))

// ldmatrix x4: 4 m8n8 b16 matrices, lane groups of 8 provide row addresses
#define LDMX4(r0, r1, r2, r3, addr) \
    asm volatile("ldmatrix.sync.aligned.m8n8.x4.shared.b16 {%0,%1,%2,%3}, [%4];" \
        : "=r"(r0), "=r"(r1), "=r"(r2), "=r"(r3) : "r"(addr))

// ---------------------------------------------------------------------------
// fp16 tensor-core GEMM, fragments via ldmatrix.
// CTA 128x128, 8 warps (4x2), warp tile 32x64, BK=32, cp.async double buffer.
// MODE 1 = QKV fused (V stored transposed); MODE 0 = fp32 output.
// ---------------------------------------------------------------------------
#define GK    D_MODEL
#define BK    32
#define NST   (GK / BK)
#define PADH  40
#define TILEH (128 * PADH)
#define GEMM_SMEM (2 * 2 * TILEH * 2)   // 40960 bytes

template <int MODE>
__global__ __launch_bounds__(256) void gemm_h_kernel(
    const __half* __restrict__ A, const __half* __restrict__ Bt,
    __half* __restrict__ HQ, __half* __restrict__ HK, __half* __restrict__ HVt,
    float* __restrict__ F0)
{
    extern __shared__ __half smh[];
    const int tid  = threadIdx.x;
    const int lane = tid & 31;
    const int wid  = tid >> 5;
    const int wm   = wid & 3;
    const int wn   = wid >> 2;
    const int g    = lane >> 2;
    const int tg   = lane & 3;
    const int m0   = blockIdx.y * 128;

    int n0, which = 0;
    const __half* Bbase = Bt;
    if (MODE == 1) {
        which = blockIdx.x >> 3;
        Bbase = Bt + (size_t)which * D_MODEL * D_MODEL;
        n0 = (blockIdx.x & 7) * 128;
    } else {
        n0 = blockIdx.x * 128;
    }

    const __half* Ab = A     + (size_t)m0 * GK;
    const __half* Bb = Bbase + (size_t)n0 * GK;

    // ldmatrix lane constants
    const int a_row  = lane & 15;            // A: matrix row within 16
    const int a_khi  = (lane >> 4) << 3;     // A: k high-half select
    const int bq     = lane >> 3;
    const int b_row  = ((bq & 2) << 2) + (lane & 7);   // B: n row within 16
    const int b_khi  = (bq & 1) << 3;                  // B: k high-half select
    const uint32_t a_loff = (uint32_t)(a_row * PADH + a_khi) * 2;
    const uint32_t b_loff = (uint32_t)(b_row * PADH + b_khi) * 2;

    float acc[2][8][4];
#pragma unroll
    for (int mi = 0; mi < 2; mi++)
#pragma unroll
        for (int ni = 0; ni < 8; ni++)
#pragma unroll
            for (int r = 0; r < 4; r++) acc[mi][ni][r] = 0.f;

    auto load_stage = [&](int s) {
        __half* dA = smh + (s & 1) * 2 * TILEH;
        __half* dB = dA + TILEH;
        const __half* Ak = Ab + s * BK;
        const __half* Bk = Bb + s * BK;
#pragma unroll
        for (int i = 0; i < 2; i++) {
            const int c   = tid + i * 256;
            const int row = c >> 2;
            const int ch  = c & 3;
            CP_ASYNC16(smem_u32(dA + row * PADH + ch * 8), Ak + (size_t)row * GK + ch * 8);
        }
#pragma unroll
        for (int i = 0; i < 2; i++) {
            const int c   = tid + i * 256;
            const int row = c >> 2;
            const int ch  = c & 3;
            CP_ASYNC16(smem_u32(dB + row * PADH + ch * 8), Bk + (size_t)row * GK + ch * 8);
        }
    };

    load_stage(0);
    CP_COMMIT();

    for (int s = 0; s < NST; s++) {
        if (s + 1 < NST) { load_stage(s + 1); CP_COMMIT(); CP_WAIT1(); }
        else             { CP_WAIT0(); }
        __syncthreads();

        const uint32_t sA32 = smem_u32(smh + (s & 1) * 2 * TILEH);
        const uint32_t sB32 = sA32 + TILEH * 2;
        const uint32_t aw   = sA32 + (uint32_t)(wm * 32 * PADH) * 2 + a_loff;
        const uint32_t bw   = sB32 + (uint32_t)(wn * 64 * PADH) * 2 + b_loff;

#pragma unroll
        for (int kk = 0; kk < 2; kk++) {
            const int k0 = kk * 16;
            uint32_t a[2][4], b[8][2];
#pragma unroll
            for (int mi = 0; mi < 2; mi++)
                LDMX4(a[mi][0], a[mi][1], a[mi][2], a[mi][3],
                      aw + (uint32_t)(mi * 16 * PADH + k0) * 2);
#pragma unroll
            for (int nip = 0; nip < 4; nip++)
                LDMX4(b[2 * nip][0], b[2 * nip][1], b[2 * nip + 1][0], b[2 * nip + 1][1],
                      bw + (uint32_t)(nip * 16 * PADH + k0) * 2);
#pragma unroll
            for (int mi = 0; mi < 2; mi++)
#pragma unroll
                for (int ni = 0; ni < 8; ni++)
                    MMA_F16(acc[mi][ni], a[mi], b[ni]);
        }
        __syncthreads();
    }

#pragma unroll
    for (int mi = 0; mi < 2; mi++) {
#pragma unroll
        for (int ni = 0; ni < 8; ni++) {
            const int r = m0 + wm * 32 + mi * 16 + g;
            const int c = n0 + wn * 64 + ni * 8 + tg * 2;
            const float v0 = acc[mi][ni][0], v1 = acc[mi][ni][1];
            const float v2 = acc[mi][ni][2], v3 = acc[mi][ni][3];
            if (MODE == 0) {
                *(float2*)&F0[(size_t)r * D_MODEL + c]       = make_float2(v0, v1);
                *(float2*)&F0[(size_t)(r + 8) * D_MODEL + c] = make_float2(v2, v3);
            } else if (which < 2) {
                __half* C = (which == 0) ? HQ : HK;
                *(__half2*)&C[(size_t)r * D_MODEL + c]       = __floats2half2_rn(v0, v1);
                *(__half2*)&C[(size_t)(r + 8) * D_MODEL + c] = __floats2half2_rn(v2, v3);
            } else {
                HVt[(size_t)c       * MROWS + r]     = __float2half_rn(v0);
                HVt[(size_t)(c + 1) * MROWS + r]     = __float2half_rn(v1);
                HVt[(size_t)c       * MROWS + r + 8] = __float2half_rn(v2);
                HVt[(size_t)(c + 1) * MROWS + r + 8] = __float2half_rn(v3);
            }
        }
    }
}

// ---------------------------------------------------------------------------
// Batched 1024x1024 transpose, fp32 -> half.
// ---------------------------------------------------------------------------
__global__ __launch_bounds__(256) void transpose4h_kernel(
    const float* __restrict__ w0, const float* __restrict__ w1,
    const float* __restrict__ w2, const float* __restrict__ w3,
    __half* __restrict__ wt, __half* __restrict__ wot)
{
    __shared__ float t[32][33];
    const int z = blockIdx.z;
    const float* in = (z == 0) ? w0 : (z == 1) ? w1 : (z == 2) ? w2 : w3;
    __half* out = (z < 3) ? (wt + (size_t)z * D_MODEL * D_MODEL) : wot;

    int x  = blockIdx.x * 32 + threadIdx.x;
    int y0 = blockIdx.y * 32 + threadIdx.y;
#pragma unroll
    for (int j = 0; j < 32; j += 8)
        t[threadIdx.y + j][threadIdx.x] = in[(size_t)(y0 + j) * D_MODEL + x];
    __syncthreads();
    x  = blockIdx.y * 32 + threadIdx.x;
    y0 = blockIdx.x * 32 + threadIdx.y;
#pragma unroll
    for (int j = 0; j < 32; j += 8)
        out[(size_t)(y0 + j) * D_MODEL + x] = __float2half_rn(t[threadIdx.x][threadIdx.y + j]);
}

__global__ __launch_bounds__(256) void convh_kernel(
    const float* __restrict__ in, __half* __restrict__ out, int n4)
{
    int i = blockIdx.x * blockDim.x + threadIdx.x;
    if (i < n4) {
        float4 v = ((const float4*)in)[i];
        __half2 h0 = __floats2half2_rn(v.x, v.y);
        __half2 h1 = __floats2half2_rn(v.z, v.w);
        ((uint2*)out)[i] = make_uint2(*(uint32_t*)&h0, *(uint32_t*)&h1);
    }
}

// ---------------------------------------------------------------------------
// fp16 flash attention v3: ldmatrix for K/V/Q fragments, P in registers,
// exp2 softmax. Block = 64 q rows; 128 threads = 4 warps x 16 q rows.
// ---------------------------------------------------------------------------
#define FPH 72
// Qs[64] + Ks[2][64] + Vts[2][64] rows of FPH halfs
#define FA_SMEM ((64 + 128 + 128) * FPH * 2)   // 46080 bytes

__global__ __launch_bounds__(128) void flash_h_kernel(
    const __half* __restrict__ Qh, const __half* __restrict__ Kh,
    const __half* __restrict__ Vt, __half* __restrict__ Ch)
{
    extern __shared__ __half fsh[];
    __half* Qs  = fsh;                      // [64][FPH]
    __half* Ksb = Qs + 64 * FPH;            // 2 x [64][FPH]
    __half* Vsb = Ksb + 2 * 64 * FPH;       // 2 x [64][FPH]

    const int tid  = threadIdx.x;
    const int lane = tid & 31;
    const int wid  = tid >> 5;
    const int g    = lane >> 2;
    const int tg   = lane & 3;
    const int b    = blockIdx.z;
    const int h    = blockIdx.y;
    const int q0   = (gridDim.x - 1 - blockIdx.x) * 64;   // heavy tiles first

    const __half* Kb  = Kh + (size_t)b * S_LEN * D_MODEL + (size_t)h * HD;
    const __half* Vtb = Vt + (size_t)h * HD * MROWS + (size_t)b * S_LEN;

    // ldmatrix lane constants (FPH stride)
    const int a_row  = lane & 15;
    const int a_khi  = (lane >> 4) << 3;
    const int bq     = lane >> 3;
    const int b_row  = ((bq & 2) << 2) + (lane & 7);
    const int b_khi  = (bq & 1) << 3;
    const uint32_t a_loff = (uint32_t)(a_row * FPH + a_khi) * 2;
    const uint32_t b_loff = (uint32_t)(b_row * FPH + b_khi) * 2;

    auto prefetch = [&](int k0, int buf) {
        __half* dK = Ksb + buf * 64 * FPH;
        __half* dV = Vsb + buf * 64 * FPH;
#pragma unroll
        for (int i = 0; i < 4; i++) {
            const int c   = tid + i * 128;
            const int row = c >> 3;
            const int ch  = c & 7;
            CP_ASYNC16(smem_u32(dK + row * FPH + ch * 8),
                       Kb + (size_t)(k0 + row) * D_MODEL + ch * 8);
        }
#pragma unroll
        for (int i = 0; i < 4; i++) {
            const int c   = tid + i * 128;
            const int row = c >> 3;
            const int ch  = c & 7;
            CP_ASYNC16(smem_u32(dV + row * FPH + ch * 8),
                       Vtb + (size_t)row * MROWS + k0 + ch * 8);
        }
    };

    // stage Q tile into smem (coalesced)
    {
        const int lrow = tid >> 1;
        const int lcol = (tid & 1) * 32;
        const __half* qp = Qh + ((size_t)(b * S_LEN + q0 + lrow)) * D_MODEL
                              + (size_t)h * HD + lcol;
#pragma unroll
        for (int c = 0; c < 32; c += 8)
            *(float4*)&Qs[lrow * FPH + lcol + c] = *(const float4*)(qp + c);
    }
    prefetch(0, 0);
    CP_COMMIT();
    __syncthreads();

    // lift Q fragments to registers (ldmatrix, 4 k16 blocks)
    uint32_t qf[4][4];
    {
        const uint32_t qw = smem_u32(Qs) + (uint32_t)(wid * 16 * FPH) * 2 + a_loff;
#pragma unroll
        for (int kk = 0; kk < 4; kk++)
            LDMX4(qf[kk][0], qf[kk][1], qf[kk][2], qf[kk][3], qw + (uint32_t)(kk * 16) * 2);
    }

    float o[8][4];
#pragma unroll
    for (int d = 0; d < 8; d++)
#pragma unroll
        for (int r = 0; r < 4; r++) o[d][r] = 0.f;
    float mrun[2] = {-1e30f, -1e30f};
    float lrun[2] = {0.f, 0.f};

    const int qrow_lo = q0 + wid * 16 + g;
    const int ntiles  = q0 / 64 + 1;
    const float sc = 0.125f * 1.44269504f;   // (1/sqrt(64)) * log2(e)

    const uint32_t ks32_0 = smem_u32(Ksb);
    const uint32_t vs32_0 = smem_u32(Vsb);

    for (int t = 0; t < ntiles; t++) {
        const int k0  = t * 64;
        const int buf = t & 1;
        if (t + 1 < ntiles) { prefetch((t + 1) * 64, buf ^ 1); CP_COMMIT(); CP_WAIT1(); }
        else                { CP_WAIT0(); }
        __syncthreads();

        const uint32_t Ksw = ks32_0 + (uint32_t)(buf * 64 * FPH) * 2 + b_loff;
        const uint32_t Vsw = vs32_0 + (uint32_t)(buf * 64 * FPH) * 2 + b_loff;

        // ---- S = Q * K^T  (log2-scaled) ----
        float sf[8][4];
#pragma unroll
        for (int nb = 0; nb < 8; nb++)
#pragma unroll
            for (int r = 0; r < 4; r++) sf[nb][r] = 0.f;

#pragma unroll
        for (int kk = 0; kk < 4; kk++) {
            const int kd = kk * 16;
#pragma unroll
            for (int nbp = 0; nbp < 4; nbp++) {
                uint32_t b0[2], b1[2];
                LDMX4(b0[0], b0[1], b1[0], b1[1],
                      Ksw + (uint32_t)(nbp * 16 * FPH + kd) * 2);
                MMA_F16(sf[2 * nbp],     qf[kk], b0);
                MMA_F16(sf[2 * nbp + 1], qf[kk], b1);
            }
        }

        // ---- scale (log2 domain) + causal mask (diagonal tile only) ----
        const bool diag = (k0 == q0);
#pragma unroll
        for (int nb = 0; nb < 8; nb++) {
#pragma unroll
            for (int r = 0; r < 4; r++) {
                float s = sf[nb][r] * sc;
                if (diag) {
                    const int kcol = k0 + nb * 8 + tg * 2 + (r & 1);
                    const int qrow = qrow_lo + (r >> 1) * 8;
                    if (kcol > qrow) s = -1e30f;
                }
                sf[nb][r] = s;
            }
        }

        // ---- online softmax in log2 domain (rows g, g+8) ----
        uint32_t plo[8], phi[8];
#pragma unroll
        for (int r = 0; r < 2; r++) {
            float mt = -1e30f;
#pragma unroll
            for (int nb = 0; nb < 8; nb++)
                mt = fmaxf(mt, fmaxf(sf[nb][r * 2], sf[nb][r * 2 + 1]));
            mt = fmaxf(mt, __shfl_xor_sync(0xFFFFFFFFu, mt, 1));
            mt = fmaxf(mt, __shfl_xor_sync(0xFFFFFFFFu, mt, 2));
            const float mnew  = fmaxf(mrun[r], mt);
            const float alpha = exp2f(mrun[r] - mnew);
            float ls = 0.f;
#pragma unroll
            for (int nb = 0; nb < 8; nb++) {
                const float p0 = exp2f(sf[nb][r * 2]     - mnew);
                const float p1 = exp2f(sf[nb][r * 2 + 1] - mnew);
                ls += p0 + p1;
                const __half2 ph = __floats2half2_rn(p0, p1);
                if (r == 0) plo[nb] = *(const uint32_t*)&ph;
                else        phi[nb] = *(const uint32_t*)&ph;
            }
            ls += __shfl_xor_sync(0xFFFFFFFFu, ls, 1);
            ls += __shfl_xor_sync(0xFFFFFFFFu, ls, 2);
            lrun[r] = lrun[r] * alpha + ls;
            mrun[r] = mnew;
#pragma unroll
            for (int d = 0; d < 8; d++) {
                o[d][r * 2]     *= alpha;
                o[d][r * 2 + 1] *= alpha;
            }
        }

        // ---- O += P * V : P already in A-fragment layout ----
#pragma unroll
        for (int kk = 0; kk < 4; kk++) {
            const int kd = kk * 16;
            uint32_t a[4];
            a[0] = plo[2 * kk];
            a[1] = phi[2 * kk];
            a[2] = plo[2 * kk + 1];
            a[3] = phi[2 * kk + 1];
#pragma unroll
            for (int dbp = 0; dbp < 4; dbp++) {
                uint32_t b0[2], b1[2];
                LDMX4(b0[0], b0[1], b1[0], b1[1],
                      Vsw + (uint32_t)(dbp * 16 * FPH + kd) * 2);
                MMA_F16(o[2 * dbp],     a, b0);
                MMA_F16(o[2 * dbp + 1], a, b1);
            }
        }
        __syncthreads();   // all warps done with buf before overwrite
    }

    // ---- epilogue: normalize, convert to half, store ----
    const float inv0 = 1.f / lrun[0];
    const float inv1 = 1.f / lrun[1];
    __half* c0 = Ch + ((size_t)(b * S_LEN + qrow_lo)) * D_MODEL + (size_t)h * HD;
    __half* c1 = c0 + 8 * D_MODEL;
#pragma unroll
    for (int db = 0; db < 8; db++) {
        const int c = db * 8 + tg * 2;
        *(__half2*)(c0 + c) = __floats2half2_rn(o[db][0] * inv0, o[db][1] * inv0);
        *(__half2*)(c1 + c) = __floats2half2_rn(o[db][2] * inv1, o[db][3] * inv1);
    }
}

// ---------------------------------------------------------------------------
extern "C" void kernel_launch(void* const* d_in, const int* in_sizes, int n_in,
                              void* d_out, int out_size)
{
    const float* X  = (const float*)d_in[0];
    const float* Wq = (const float*)d_in[1];
    const float* Wk = (const float*)d_in[2];
    const float* Wv = (const float*)d_in[3];
    const float* Wo = (const float*)d_in[4];
    float* out = (float*)d_out;

    __half *Xh, *Qh, *Kh, *Vt, *Ch, *WTh, *WoTh;
    cudaGetSymbolAddress((void**)&Xh,   g_Xh);
    cudaGetSymbolAddress((void**)&Qh,   g_Qh);
    cudaGetSymbolAddress((void**)&Kh,   g_Kh);
    cudaGetSymbolAddress((void**)&Vt,   g_Vt);
    cudaGetSymbolAddress((void**)&Ch,   g_Ch);
    cudaGetSymbolAddress((void**)&WTh,  g_WTh);
    cudaGetSymbolAddress((void**)&WoTh, g_WoTh);

    cudaFuncSetAttribute(gemm_h_kernel<0>,
                         cudaFuncAttributeMaxDynamicSharedMemorySize, GEMM_SMEM);
    cudaFuncSetAttribute(gemm_h_kernel<1>,
                         cudaFuncAttributeMaxDynamicSharedMemorySize, GEMM_SMEM);
    cudaFuncSetAttribute(flash_h_kernel,
                         cudaFuncAttributeMaxDynamicSharedMemorySize, FA_SMEM);

    convh_kernel<<<(MROWS * D_MODEL / 4 + 255) / 256, 256>>>(X, Xh, MROWS * D_MODEL / 4);
    dim3 tr_grid(32, 32, 4), tr_blk(32, 8);
    transpose4h_kernel<<<tr_grid, tr_blk>>>(Wq, Wk, Wv, Wo, WTh, WoTh);

    dim3 qkv_grid(24, MROWS / 128);
    gemm_h_kernel<1><<<qkv_grid, 256, GEMM_SMEM>>>(Xh, WTh, Qh, Kh, Vt, nullptr);

    dim3 fa_grid(S_LEN / 64, NH, BATCH);
    flash_h_kernel<<<fa_grid, 128, FA_SMEM>>>(Qh, Kh, Vt, Ch);

    dim3 o_grid(D_MODEL / 128, MROWS / 128);
    gemm_h_kernel<0><<<o_grid, 256, GEMM_SMEM>>>(Ch, WoTh, nullptr, nullptr, nullptr, out);
}

// round 17
// speedup vs baseline: 8.2524x; 1.0319x over previous
#include <cuda_runtime.h>
#include <cuda_fp16.h>
#include <cstdint>

// Problem constants
#define BATCH   2
#define S_LEN   2048
#define D_MODEL 1024
#define NH      16
#define HD      64
#define MROWS   (BATCH * S_LEN)   // 4096

// Scratch (allocation-free rule: __device__ globals)
__device__ __half g_Xh [MROWS * D_MODEL];
__device__ __half g_Qh [MROWS * D_MODEL];      // pre-scaled by 0.125*log2(e)
__device__ __half g_Kh [MROWS * D_MODEL];
__device__ __half g_Vt [D_MODEL * MROWS];      // transposed V: [h*64+d][token]
__device__ __half g_Ch [MROWS * D_MODEL];      // attention output (half)
__device__ __half g_WTh[3 * D_MODEL * D_MODEL];// WqT | WkT | WvT (K-major, half)
__device__ __half g_WoTh[D_MODEL * D_MODEL];

// ---------------------------------------------------------------------------
// Helpers
// ---------------------------------------------------------------------------
__device__ __forceinline__ uint32_t smem_u32(const void* p) {
    uint32_t a;
    asm("{ .reg .u64 t; cvta.to.shared.u64 t, %1; cvt.u32.u64 %0, t; }"
        : "=r"(a) : "l"(p));
    return a;
}

#define CP_ASYNC16(dst, src) \
    asm volatile("cp.async.cg.shared.global [%0], [%1], 16;" :: "r"(dst), "l"(src))
#define CP_COMMIT() asm volatile("cp.async.commit_group;" ::: "memory")
#define CP_WAIT0()  asm volatile("cp.async.wait_group 0;" ::: "memory")
#define CP_WAIT1()  asm volatile("cp.async.wait_group 1;" ::: "memory")

// mma.sync m16n8k16 fp16, fp32 accumulate
#define MMA_F16(d, a, b) \
    asm volatile( \
        "mma.sync.aligned.m16n8k16.row.col.f32.f16.f16.f32 " \
        "{%0,%1,%2,%3}, {%4,%5,%6,%7}, {%8,%9}, {%0,%1,%2,%3};" \
        : "+f"((d)[0]), "+f"((d)[1]), "+f"((d)[2]), "+f"((d)[3]) \
        : "r"((a)[0]), "r"((a)[1]), "r"((a)[2]), "r"((a)[3]), \
          "r"((b)[0]), "r"((b)[1]))

// ldmatrix x4: 4 m8n8 b16 matrices, lane groups of 8 provide row addresses
#define LDMX4(r0, r1, r2, r3, addr) \
    asm volatile("ldmatrix.sync.aligned.m8n8.x4.shared.b16 {%0,%1,%2,%3}, [%4];" \
        : "=r"(r0), "=r"(r1), "=r"(r2), "=r"(r3) : "r"(addr))

#define SCQ 0.180336887f   // 0.125 * log2(e), folded into Q

// ---------------------------------------------------------------------------
// fp16 tensor-core GEMM, fragments via ldmatrix, 3-stage cp.async ring.
// CTA 128x128, 8 warps (4x2), warp tile 32x64, BK=32.
// MODE 1 = QKV fused (Q pre-scaled, V stored transposed); MODE 0 = fp32 out.
// ---------------------------------------------------------------------------
#define GK    D_MODEL
#define BK    32
#define NST   (GK / BK)
#define PADH  40
#define TILEH (128 * PADH)
#define GEMM_SMEM (3 * 2 * TILEH * 2)   // 61440 bytes

template <int MODE>
__global__ __launch_bounds__(256) void gemm_h_kernel(
    const __half* __restrict__ A, const __half* __restrict__ Bt,
    __half* __restrict__ HQ, __half* __restrict__ HK, __half* __restrict__ HVt,
    float* __restrict__ F0)
{
    extern __shared__ __half smh[];
    const int tid  = threadIdx.x;
    const int lane = tid & 31;
    const int wid  = tid >> 5;
    const int wm   = wid & 3;
    const int wn   = wid >> 2;
    const int g    = lane >> 2;
    const int tg   = lane & 3;
    const int m0   = blockIdx.y * 128;

    int n0, which = 0;
    const __half* Bbase = Bt;
    if (MODE == 1) {
        which = blockIdx.x >> 3;
        Bbase = Bt + (size_t)which * D_MODEL * D_MODEL;
        n0 = (blockIdx.x & 7) * 128;
    } else {
        n0 = blockIdx.x * 128;
    }

    const __half* Ab = A     + (size_t)m0 * GK;
    const __half* Bb = Bbase + (size_t)n0 * GK;

    // ldmatrix lane constants
    const int a_row  = lane & 15;
    const int a_khi  = (lane >> 4) << 3;
    const int bq     = lane >> 3;
    const int b_row  = ((bq & 2) << 2) + (lane & 7);
    const int b_khi  = (bq & 1) << 3;
    const uint32_t a_loff = (uint32_t)(a_row * PADH + a_khi) * 2;
    const uint32_t b_loff = (uint32_t)(b_row * PADH + b_khi) * 2;

    float acc[2][8][4];
#pragma unroll
    for (int mi = 0; mi < 2; mi++)
#pragma unroll
        for (int ni = 0; ni < 8; ni++)
#pragma unroll
            for (int r = 0; r < 4; r++) acc[mi][ni][r] = 0.f;

    auto load_stage = [&](int s) {
        __half* dA = smh + (s % 3) * 2 * TILEH;
        __half* dB = dA + TILEH;
        const __half* Ak = Ab + s * BK;
        const __half* Bk = Bb + s * BK;
#pragma unroll
        for (int i = 0; i < 2; i++) {
            const int c   = tid + i * 256;
            const int row = c >> 2;
            const int ch  = c & 3;
            CP_ASYNC16(smem_u32(dA + row * PADH + ch * 8), Ak + (size_t)row * GK + ch * 8);
        }
#pragma unroll
        for (int i = 0; i < 2; i++) {
            const int c   = tid + i * 256;
            const int row = c >> 2;
            const int ch  = c & 3;
            CP_ASYNC16(smem_u32(dB + row * PADH + ch * 8), Bk + (size_t)row * GK + ch * 8);
        }
    };

    load_stage(0); CP_COMMIT();
    load_stage(1); CP_COMMIT();

    for (int s = 0; s < NST; s++) {
        if (s + 1 < NST) { CP_WAIT1(); } else { CP_WAIT0(); }
        __syncthreads();
        if (s + 2 < NST) { load_stage(s + 2); CP_COMMIT(); }

        const uint32_t sA32 = smem_u32(smh + (s % 3) * 2 * TILEH);
        const uint32_t sB32 = sA32 + TILEH * 2;
        const uint32_t aw   = sA32 + (uint32_t)(wm * 32 * PADH) * 2 + a_loff;
        const uint32_t bw   = sB32 + (uint32_t)(wn * 64 * PADH) * 2 + b_loff;

#pragma unroll
        for (int kk = 0; kk < 2; kk++) {
            const int k0 = kk * 16;
            uint32_t a[2][4], b[8][2];
#pragma unroll
            for (int mi = 0; mi < 2; mi++)
                LDMX4(a[mi][0], a[mi][1], a[mi][2], a[mi][3],
                      aw + (uint32_t)(mi * 16 * PADH + k0) * 2);
#pragma unroll
            for (int nip = 0; nip < 4; nip++)
                LDMX4(b[2 * nip][0], b[2 * nip][1], b[2 * nip + 1][0], b[2 * nip + 1][1],
                      bw + (uint32_t)(nip * 16 * PADH + k0) * 2);
#pragma unroll
            for (int mi = 0; mi < 2; mi++)
#pragma unroll
                for (int ni = 0; ni < 8; ni++)
                    MMA_F16(acc[mi][ni], a[mi], b[ni]);
        }
        __syncthreads();
    }

#pragma unroll
    for (int mi = 0; mi < 2; mi++) {
#pragma unroll
        for (int ni = 0; ni < 8; ni++) {
            const int r = m0 + wm * 32 + mi * 16 + g;
            const int c = n0 + wn * 64 + ni * 8 + tg * 2;
            float v0 = acc[mi][ni][0], v1 = acc[mi][ni][1];
            float v2 = acc[mi][ni][2], v3 = acc[mi][ni][3];
            if (MODE == 0) {
                *(float2*)&F0[(size_t)r * D_MODEL + c]       = make_float2(v0, v1);
                *(float2*)&F0[(size_t)(r + 8) * D_MODEL + c] = make_float2(v2, v3);
            } else if (which < 2) {
                if (which == 0) { v0 *= SCQ; v1 *= SCQ; v2 *= SCQ; v3 *= SCQ; }
                __half* C = (which == 0) ? HQ : HK;
                *(__half2*)&C[(size_t)r * D_MODEL + c]       = __floats2half2_rn(v0, v1);
                *(__half2*)&C[(size_t)(r + 8) * D_MODEL + c] = __floats2half2_rn(v2, v3);
            } else {
                HVt[(size_t)c       * MROWS + r]     = __float2half_rn(v0);
                HVt[(size_t)(c + 1) * MROWS + r]     = __float2half_rn(v1);
                HVt[(size_t)c       * MROWS + r + 8] = __float2half_rn(v2);
                HVt[(size_t)(c + 1) * MROWS + r + 8] = __float2half_rn(v3);
            }
        }
    }
}

// ---------------------------------------------------------------------------
// Batched 1024x1024 transpose, fp32 -> half.
// ---------------------------------------------------------------------------
__global__ __launch_bounds__(256) void transpose4h_kernel(
    const float* __restrict__ w0, const float* __restrict__ w1,
    const float* __restrict__ w2, const float* __restrict__ w3,
    __half* __restrict__ wt, __half* __restrict__ wot)
{
    __shared__ float t[32][33];
    const int z = blockIdx.z;
    const float* in = (z == 0) ? w0 : (z == 1) ? w1 : (z == 2) ? w2 : w3;
    __half* out = (z < 3) ? (wt + (size_t)z * D_MODEL * D_MODEL) : wot;

    int x  = blockIdx.x * 32 + threadIdx.x;
    int y0 = blockIdx.y * 32 + threadIdx.y;
#pragma unroll
    for (int j = 0; j < 32; j += 8)
        t[threadIdx.y + j][threadIdx.x] = in[(size_t)(y0 + j) * D_MODEL + x];
    __syncthreads();
    x  = blockIdx.y * 32 + threadIdx.x;
    y0 = blockIdx.x * 32 + threadIdx.y;
#pragma unroll
    for (int j = 0; j < 32; j += 8)
        out[(size_t)(y0 + j) * D_MODEL + x] = __float2half_rn(t[threadIdx.x][threadIdx.y + j]);
}

__global__ __launch_bounds__(256) void convh_kernel(
    const float* __restrict__ in, __half* __restrict__ out, int n4)
{
    int i = blockIdx.x * blockDim.x + threadIdx.x;
    if (i < n4) {
        float4 v = ((const float4*)in)[i];
        __half2 h0 = __floats2half2_rn(v.x, v.y);
        __half2 h1 = __floats2half2_rn(v.z, v.w);
        ((uint2*)out)[i] = make_uint2(*(uint32_t*)&h0, *(uint32_t*)&h1);
    }
}

// ---------------------------------------------------------------------------
// fp16 flash attention v4: scores come pre-scaled (Q carries 0.125*log2e),
// warp-uniform rescale skip, ldmatrix fragments, P in registers.
// Block = 64 q rows; 128 threads = 4 warps x 16 q rows.
// ---------------------------------------------------------------------------
#define FPH 72
#define FA_SMEM ((64 + 128 + 128) * FPH * 2)   // 46080 bytes

__global__ __launch_bounds__(128) void flash_h_kernel(
    const __half* __restrict__ Qh, const __half* __restrict__ Kh,
    const __half* __restrict__ Vt, __half* __restrict__ Ch)
{
    extern __shared__ __half fsh[];
    __half* Qs  = fsh;                      // [64][FPH]
    __half* Ksb = Qs + 64 * FPH;            // 2 x [64][FPH]
    __half* Vsb = Ksb + 2 * 64 * FPH;       // 2 x [64][FPH]

    const int tid  = threadIdx.x;
    const int lane = tid & 31;
    const int wid  = tid >> 5;
    const int g    = lane >> 2;
    const int tg   = lane & 3;
    const int b    = blockIdx.z;
    const int h    = blockIdx.y;
    const int q0   = (gridDim.x - 1 - blockIdx.x) * 64;   // heavy tiles first

    const __half* Kb  = Kh + (size_t)b * S_LEN * D_MODEL + (size_t)h * HD;
    const __half* Vtb = Vt + (size_t)h * HD * MROWS + (size_t)b * S_LEN;

    // ldmatrix lane constants (FPH stride)
    const int a_row  = lane & 15;
    const int a_khi  = (lane >> 4) << 3;
    const int bq     = lane >> 3;
    const int b_row  = ((bq & 2) << 2) + (lane & 7);
    const int b_khi  = (bq & 1) << 3;
    const uint32_t a_loff = (uint32_t)(a_row * FPH + a_khi) * 2;
    const uint32_t b_loff = (uint32_t)(b_row * FPH + b_khi) * 2;

    auto prefetch = [&](int k0, int buf) {
        __half* dK = Ksb + buf * 64 * FPH;
        __half* dV = Vsb + buf * 64 * FPH;
#pragma unroll
        for (int i = 0; i < 4; i++) {
            const int c   = tid + i * 128;
            const int row = c >> 3;
            const int ch  = c & 7;
            CP_ASYNC16(smem_u32(dK + row * FPH + ch * 8),
                       Kb + (size_t)(k0 + row) * D_MODEL + ch * 8);
        }
#pragma unroll
        for (int i = 0; i < 4; i++) {
            const int c   = tid + i * 128;
            const int row = c >> 3;
            const int ch  = c & 7;
            CP_ASYNC16(smem_u32(dV + row * FPH + ch * 8),
                       Vtb + (size_t)row * MROWS + k0 + ch * 8);
        }
    };

    // stage Q tile into smem (coalesced)
    {
        const int lrow = tid >> 1;
        const int lcol = (tid & 1) * 32;
        const __half* qp = Qh + ((size_t)(b * S_LEN + q0 + lrow)) * D_MODEL
                              + (size_t)h * HD + lcol;
#pragma unroll
        for (int c = 0; c < 32; c += 8)
            *(float4*)&Qs[lrow * FPH + lcol + c] = *(const float4*)(qp + c);
    }
    prefetch(0, 0);
    CP_COMMIT();
    __syncthreads();

    // lift Q fragments to registers (ldmatrix, 4 k16 blocks)
    uint32_t qf[4][4];
    {
        const uint32_t qw = smem_u32(Qs) + (uint32_t)(wid * 16 * FPH) * 2 + a_loff;
#pragma unroll
        for (int kk = 0; kk < 4; kk++)
            LDMX4(qf[kk][0], qf[kk][1], qf[kk][2], qf[kk][3], qw + (uint32_t)(kk * 16) * 2);
    }

    float o[8][4];
#pragma unroll
    for (int d = 0; d < 8; d++)
#pragma unroll
        for (int r = 0; r < 4; r++) o[d][r] = 0.f;
    float mrun[2] = {-1e30f, -1e30f};
    float lrun[2] = {0.f, 0.f};

    const int qrow_lo = q0 + wid * 16 + g;
    const int ntiles  = q0 / 64 + 1;

    const uint32_t ks32_0 = smem_u32(Ksb);
    const uint32_t vs32_0 = smem_u32(Vsb);

    for (int t = 0; t < ntiles; t++) {
        const int k0  = t * 64;
        const int buf = t & 1;
        if (t + 1 < ntiles) { prefetch((t + 1) * 64, buf ^ 1); CP_COMMIT(); CP_WAIT1(); }
        else                { CP_WAIT0(); }
        __syncthreads();

        const uint32_t Ksw = ks32_0 + (uint32_t)(buf * 64 * FPH) * 2 + b_loff;
        const uint32_t Vsw = vs32_0 + (uint32_t)(buf * 64 * FPH) * 2 + b_loff;

        // ---- S = Q * K^T  (already log2-scaled via Q) ----
        float sf[8][4];
#pragma unroll
        for (int nb = 0; nb < 8; nb++)
#pragma unroll
            for (int r = 0; r < 4; r++) sf[nb][r] = 0.f;

#pragma unroll
        for (int kk = 0; kk < 4; kk++) {
            const int kd = kk * 16;
#pragma unroll
            for (int nbp = 0; nbp < 4; nbp++) {
                uint32_t b0[2], b1[2];
                LDMX4(b0[0], b0[1], b1[0], b1[1],
                      Ksw + (uint32_t)(nbp * 16 * FPH + kd) * 2);
                MMA_F16(sf[2 * nbp],     qf[kk], b0);
                MMA_F16(sf[2 * nbp + 1], qf[kk], b1);
            }
        }

        // ---- causal mask (diagonal tile only) ----
        if (k0 == q0) {
#pragma unroll
            for (int nb = 0; nb < 8; nb++) {
#pragma unroll
                for (int r = 0; r < 4; r++) {
                    const int kcol = k0 + nb * 8 + tg * 2 + (r & 1);
                    const int qrow = qrow_lo + (r >> 1) * 8;
                    if (kcol > qrow) sf[nb][r] = -1e30f;
                }
            }
        }

        // ---- online softmax in log2 domain (rows g, g+8) ----
        uint32_t plo[8], phi[8];
#pragma unroll
        for (int r = 0; r < 2; r++) {
            float mt = -1e30f;
#pragma unroll
            for (int nb = 0; nb < 8; nb++)
                mt = fmaxf(mt, fmaxf(sf[nb][r * 2], sf[nb][r * 2 + 1]));
            mt = fmaxf(mt, __shfl_xor_sync(0xFFFFFFFFu, mt, 1));
            mt = fmaxf(mt, __shfl_xor_sync(0xFFFFFFFFu, mt, 2));
            float alpha = 1.f;
            if (__any_sync(0xFFFFFFFFu, mt > mrun[r])) {
                const float mnew = fmaxf(mrun[r], mt);
                alpha = exp2f(mrun[r] - mnew);
                mrun[r] = mnew;
#pragma unroll
                for (int d = 0; d < 8; d++) {
                    o[d][r * 2]     *= alpha;
                    o[d][r * 2 + 1] *= alpha;
                }
            }
            const float m = mrun[r];
            float ls = 0.f;
#pragma unroll
            for (int nb = 0; nb < 8; nb++) {
                const float p0 = exp2f(sf[nb][r * 2]     - m);
                const float p1 = exp2f(sf[nb][r * 2 + 1] - m);
                ls += p0 + p1;
                const __half2 ph = __floats2half2_rn(p0, p1);
                if (r == 0) plo[nb] = *(const uint32_t*)&ph;
                else        phi[nb] = *(const uint32_t*)&ph;
            }
            ls += __shfl_xor_sync(0xFFFFFFFFu, ls, 1);
            ls += __shfl_xor_sync(0xFFFFFFFFu, ls, 2);
            lrun[r] = lrun[r] * alpha + ls;
        }

        // ---- O += P * V : P already in A-fragment layout ----
#pragma unroll
        for (int kk = 0; kk < 4; kk++) {
            const int kd = kk * 16;
            uint32_t a[4];
            a[0] = plo[2 * kk];
            a[1] = phi[2 * kk];
            a[2] = plo[2 * kk + 1];
            a[3] = phi[2 * kk + 1];
#pragma unroll
            for (int dbp = 0; dbp < 4; dbp++) {
                uint32_t b0[2], b1[2];
                LDMX4(b0[0], b0[1], b1[0], b1[1],
                      Vsw + (uint32_t)(dbp * 16 * FPH + kd) * 2);
                MMA_F16(o[2 * dbp],     a, b0);
                MMA_F16(o[2 * dbp + 1], a, b1);
            }
        }
        __syncthreads();   // all warps done with buf before overwrite
    }

    // ---- epilogue: normalize, convert to half, store ----
    const float inv0 = 1.f / lrun[0];
    const float inv1 = 1.f / lrun[1];
    __half* c0 = Ch + ((size_t)(b * S_LEN + qrow_lo)) * D_MODEL + (size_t)h * HD;
    __half* c1 = c0 + 8 * D_MODEL;
#pragma unroll
    for (int db = 0; db < 8; db++) {
        const int c = db * 8 + tg * 2;
        *(__half2*)(c0 + c) = __floats2half2_rn(o[db][0] * inv0, o[db][1] * inv0);
        *(__half2*)(c1 + c) = __floats2half2_rn(o[db][2] * inv1, o[db][3] * inv1);
    }
}

// ---------------------------------------------------------------------------
extern "C" void kernel_launch(void* const* d_in, const int* in_sizes, int n_in,
                              void* d_out, int out_size)
{
    const float* X  = (const float*)d_in[0];
    const float* Wq = (const float*)d_in[1];
    const float* Wk = (const float*)d_in[2];
    const float* Wv = (const float*)d_in[3];
    const float* Wo = (const float*)d_in[4];
    float* out = (float*)d_out;

    __half *Xh, *Qh, *Kh, *Vt, *Ch, *WTh, *WoTh;
    cudaGetSymbolAddress((void**)&Xh,   g_Xh);
    cudaGetSymbolAddress((void**)&Qh,   g_Qh);
    cudaGetSymbolAddress((void**)&Kh,   g_Kh);
    cudaGetSymbolAddress((void**)&Vt,   g_Vt);
    cudaGetSymbolAddress((void**)&Ch,   g_Ch);
    cudaGetSymbolAddress((void**)&WTh,  g_WTh);
    cudaGetSymbolAddress((void**)&WoTh, g_WoTh);

    cudaFuncSetAttribute(gemm_h_kernel<0>,
                         cudaFuncAttributeMaxDynamicSharedMemorySize, GEMM_SMEM);
    cudaFuncSetAttribute(gemm_h_kernel<1>,
                         cudaFuncAttributeMaxDynamicSharedMemorySize, GEMM_SMEM);
    cudaFuncSetAttribute(flash_h_kernel,
                         cudaFuncAttributeMaxDynamicSharedMemorySize, FA_SMEM);

    convh_kernel<<<(MROWS * D_MODEL / 4 + 255) / 256, 256>>>(X, Xh, MROWS * D_MODEL / 4);
    dim3 tr_grid(32, 32, 4), tr_blk(32, 8);
    transpose4h_kernel<<<tr_grid, tr_blk>>>(Wq, Wk, Wv, Wo, WTh, WoTh);

    dim3 qkv_grid(24, MROWS / 128);
    gemm_h_kernel<1><<<qkv_grid, 256, GEMM_SMEM>>>(Xh, WTh, Qh, Kh, Vt, nullptr);

    dim3 fa_grid(S_LEN / 64, NH, BATCH);
    flash_h_kernel<<<fa_grid, 128, FA_SMEM>>>(Qh, Kh, Vt, Ch);

    dim3 o_grid(D_MODEL / 128, MROWS / 128);
    gemm_h_kernel<0><<<o_grid, 256, GEMM_SMEM>>>(Ch, WoTh, nullptr, nullptr, nullptr, out);
}